// round 15
// baseline (speedup 1.0000x reference)
#include <cuda_runtime.h>
#include <cuda_bf16.h>
#include <math.h>
#include <stdint.h>

// Problem constants
#define BB   8
#define LQ   512
#define LKV  1024
#define DD   1024
#define HH_  16
#define HD   64
#define LN_EPS 1e-5f

#define S_SCALE   4096.0f
#define S_INVSC   (1.0f / 4096.0f)
#define PART_STRIDE (BB * HH_ * LQ)   // 65536 rows

// ---------------------------------------------------------------------------
// Scratch (device globals: allocation-free per harness rules)
// ---------------------------------------------------------------------------
__device__ __align__(16) short g_S[(size_t)BB * HH_ * LQ * LKV];          // int16 scores
__device__ __align__(16) __nv_bfloat16 g_P[(size_t)BB * HH_ * LQ * LKV]; // e=exp(s) bf16
__device__ float g_part[8 * PART_STRIDE];            // per-(row, nblock) rowsum partials
__device__ float g_AO  [BB * LQ  * DD];              // fp32 attn_out

// bf16 buffers
__device__ __align__(16) __nv_bfloat16 g_qh [BB * LQ  * DD], g_ql [BB * LQ  * DD];
__device__ __align__(16) __nv_bfloat16 g_kh [BB * LKV * DD], g_kl [BB * LKV * DD];
__device__ __align__(16) __nv_bfloat16 g_vh [BB * LKV * DD];   // value input hi
__device__ __align__(16) __nv_bfloat16 g_vt [BB * LKV * DD];   // Vt head-major bf16
__device__ __align__(16) __nv_bfloat16 g_wh [3 * DD * DD],   g_wl [3 * DD * DD];
__device__ __align__(16) __nv_bfloat16 g_woh[DD * DD];
__device__ __align__(16) __nv_bfloat16 g_qh2[BB * LQ  * DD], g_ql2[BB * LQ  * DD];
__device__ __align__(16) __nv_bfloat16 g_kh2[BB * LKV * DD], g_kl2[BB * LKV * DD];
__device__ __align__(16) __nv_bfloat16 g_ch [BB * LQ  * DD];

// ---------------------------------------------------------------------------
// Baseline-PTX tensor-core helpers (NO tcgen05 — compute_103 target!)
// ---------------------------------------------------------------------------
__device__ __forceinline__ uint32_t smem_u32(const void* p) {
    uint32_t a;
    asm("{ .reg .u64 t; cvta.to.shared.u64 t, %1; cvt.u32.u64 %0, t; }" : "=r"(a) : "l"(p));
    return a;
}
__device__ __forceinline__ void ldsm4(uint32_t& r0, uint32_t& r1, uint32_t& r2,
                                      uint32_t& r3, uint32_t a) {
    asm volatile("ldmatrix.sync.aligned.m8n8.x4.shared.b16 {%0,%1,%2,%3}, [%4];"
                 : "=r"(r0), "=r"(r1), "=r"(r2), "=r"(r3) : "r"(a));
}
__device__ __forceinline__ void mma_bf16(float* d, const uint32_t* a, const uint32_t* b) {
    asm volatile("mma.sync.aligned.m16n8k16.row.col.f32.bf16.bf16.f32 "
                 "{%0,%1,%2,%3},{%4,%5,%6,%7},{%8,%9},{%0,%1,%2,%3};"
                 : "+f"(d[0]), "+f"(d[1]), "+f"(d[2]), "+f"(d[3])
                 : "r"(a[0]), "r"(a[1]), "r"(a[2]), "r"(a[3]), "r"(b[0]), "r"(b[1]));
}
#define CP_ASYNC16(s, g) \
    asm volatile("cp.async.cg.shared.global [%0], [%1], 16;" :: "r"(s), "l"(g))
#define CP_COMMIT() asm volatile("cp.async.commit_group;" ::: "memory")
#define CP_WAIT1()  asm volatile("cp.async.wait_group 1;"  ::: "memory")

// 128B-row XOR swizzle: 16B chunk c (0..7), row r
__device__ __forceinline__ uint32_t sw128(int r, int c) {
    return (uint32_t)(r * 128 + ((c ^ (r & 7)) << 4));
}
__device__ __forceinline__ void bsplit(float v, __nv_bfloat16& h, __nv_bfloat16& l) {
    h = __float2bfloat16(v);
    l = __float2bfloat16(v - __bfloat162float(h));
}
__device__ __forceinline__ short squant(float v) {
    v = fminf(fmaxf(v, -32700.f), 32700.f);
    return (short)__float2int_rn(v);
}

// ---------------------------------------------------------------------------
// One launch: split all inputs/weights (hi/lo or hi-only per segment)
// ---------------------------------------------------------------------------
__device__ __forceinline__ void seg_split2(float4 v, __nv_bfloat162* hi,
                                           __nv_bfloat162* lo, long i) {
    __nv_bfloat16 h0, h1, h2, h3, l0, l1, l2, l3;
    bsplit(v.x, h0, l0); bsplit(v.y, h1, l1);
    bsplit(v.z, h2, l2); bsplit(v.w, h3, l3);
    hi[i * 2 + 0] = __halves2bfloat162(h0, h1);
    hi[i * 2 + 1] = __halves2bfloat162(h2, h3);
    lo[i * 2 + 0] = __halves2bfloat162(l0, l1);
    lo[i * 2 + 1] = __halves2bfloat162(l2, l3);
}
__device__ __forceinline__ void seg_split1(float4 v, __nv_bfloat162* hi, long i) {
    hi[i * 2 + 0] = __halves2bfloat162(__float2bfloat16(v.x), __float2bfloat16(v.y));
    hi[i * 2 + 1] = __halves2bfloat162(__float2bfloat16(v.z), __float2bfloat16(v.w));
}

__global__ void split_all(const float4* __restrict__ q, const float4* __restrict__ k,
                          const float4* __restrict__ v, const float4* __restrict__ w,
                          const float4* __restrict__ wo,
                          __nv_bfloat162* qh, __nv_bfloat162* ql,
                          __nv_bfloat162* kh, __nv_bfloat162* kl,
                          __nv_bfloat162* vh,
                          __nv_bfloat162* wh, __nv_bfloat162* wl,
                          __nv_bfloat162* woh)
{
    const long N1 = (long)BB * LQ * DD / 4;
    const long N2 = N1 + (long)BB * LKV * DD / 4;
    const long N3 = N2 + (long)BB * LKV * DD / 4;
    const long N4 = N3 + 3L * DD * DD / 4;
    const long N5 = N4 + (long)DD * DD / 4;
    long i = (long)blockIdx.x * blockDim.x + threadIdx.x;
    if (i < N1)      seg_split2(q[i], qh, ql, i);
    else if (i < N2) { i -= N1; seg_split2(k[i], kh, kl, i); }
    else if (i < N3) { i -= N2; seg_split1(v[i], vh, i); }
    else if (i < N4) { i -= N3; seg_split2(w[i], wh, wl, i); }
    else if (i < N5) { i -= N4; seg_split1(wo[i], woh, i); }
}

// ---------------------------------------------------------------------------
// Merged Q/K/V projection. Grid (8, 160): y<32 Q, y<96 K, else V.
// ---------------------------------------------------------------------------
__global__ void __launch_bounds__(128, 2) qkv_proj(
    const __nv_bfloat16* __restrict__ qhp, const __nv_bfloat16* __restrict__ qlp,
    const __nv_bfloat16* __restrict__ khp, const __nv_bfloat16* __restrict__ klp,
    const __nv_bfloat16* __restrict__ vhp,
    const __nv_bfloat16* __restrict__ whp, const __nv_bfloat16* __restrict__ wlp,
    const float* __restrict__ in_b,
    __nv_bfloat16* __restrict__ qh2, __nv_bfloat16* __restrict__ ql2,
    __nv_bfloat16* __restrict__ kh2, __nv_bfloat16* __restrict__ kl2,
    __nv_bfloat16* __restrict__ vt, float qscale)
{
    extern __shared__ __align__(16) char dynsm[];
    const uint32_t smBase = smem_u32(dynsm);

    const int tid  = threadIdx.x;
    const int lane = tid & 31;
    const int wid  = tid >> 5;
    const int wr   = wid >> 1;
    const int wc   = wid & 1;
    const int y    = blockIdx.y;
    const int n0   = blockIdx.x * 128;

    int region, m0, NIT;
    float scale = 1.0f;
    const __nv_bfloat16 *Ahi, *Alo, *Bhi, *Blo;
    const float* bias;
    if (y < 32) {
        region = 0; m0 = y * 128; NIT = 48; scale = qscale;
        Ahi = qhp; Alo = qlp; Bhi = whp; Blo = wlp; bias = in_b;
    } else if (y < 96) {
        region = 1; m0 = (y - 32) * 128; NIT = 48;
        Ahi = khp; Alo = klp;
        Bhi = whp + (size_t)DD * DD; Blo = wlp + (size_t)DD * DD;
        bias = in_b + DD;
    } else {
        region = 2; m0 = (y - 96) * 128; NIT = 16;
        Ahi = vhp; Alo = vhp;
        Bhi = whp + 2ul * DD * DD; Blo = Bhi;
        bias = in_b + 2 * DD;
    }

    const int rA  = lane & 15;
    const int cAh = lane >> 4;
    const int rBl = (lane & 7) + ((lane & 16) >> 1);
    const int cBh = (lane >> 3) & 1;

    float acc[4][8][4];
#pragma unroll
    for (int mt = 0; mt < 4; ++mt)
#pragma unroll
        for (int nt = 0; nt < 8; ++nt)
#pragma unroll
            for (int j = 0; j < 4; ++j) acc[mt][nt][j] = 0.f;

    auto prefetch = [&](int it, int stage) {
        const int part = it >> 4;
        const int ko   = (it & 15) << 6;
        const __nv_bfloat16* Ap = (part == 2) ? Alo : Ahi;
        const __nv_bfloat16* Bp = (part == 1) ? Blo : Bhi;
        const uint32_t as = smBase + (uint32_t)stage * 32768u;
        const uint32_t bs = as + 16384u;
#pragma unroll
        for (int i = 0; i < 8; ++i) {
            int q = i * 128 + tid;
            int r = q >> 3, c = q & 7;
            CP_ASYNC16(as + sw128(r, c),
                       Ap + (((size_t)(m0 + r)) << 10) + ko + c * 8);
            CP_ASYNC16(bs + sw128(r, c),
                       Bp + (((size_t)(n0 + r)) << 10) + ko + c * 8);
        }
        CP_COMMIT();
    };

    prefetch(0, 0);
    prefetch(1, 1);

    for (int it = 0; it < NIT; ++it) {
        CP_WAIT1();
        __syncthreads();
        if (it + 2 < NIT) prefetch(it + 2, (it + 2) % 3);
        else CP_COMMIT();

        const uint32_t aT = smBase + (uint32_t)(it % 3) * 32768u;
        const uint32_t bT = aT + 16384u;

#pragma unroll
        for (int ks = 0; ks < 4; ++ks) {
            uint32_t af[4][4];
            uint32_t bf[8][2];
#pragma unroll
            for (int mt = 0; mt < 4; ++mt) {
                int r = wr * 64 + mt * 16 + rA;
                ldsm4(af[mt][0], af[mt][1], af[mt][2], af[mt][3],
                      aT + sw128(r, ks * 2 + cAh));
            }
#pragma unroll
            for (int tp = 0; tp < 4; ++tp) {
                int r = wc * 64 + tp * 16 + rBl;
                uint32_t x0, x1, x2, x3;
                ldsm4(x0, x1, x2, x3, bT + sw128(r, ks * 2 + cBh));
                bf[tp * 2][0] = x0;     bf[tp * 2][1] = x1;
                bf[tp * 2 + 1][0] = x2; bf[tp * 2 + 1][1] = x3;
            }
#pragma unroll
            for (int mt = 0; mt < 4; ++mt)
#pragma unroll
                for (int nt = 0; nt < 8; ++nt)
                    mma_bf16(acc[mt][nt], af[mt], bf[nt]);
        }
    }
    __syncthreads();

    if (region < 2) {
        __nv_bfloat16* Chi = region ? kh2 : qh2;
        __nv_bfloat16* Clo = region ? kl2 : ql2;
#pragma unroll
        for (int mt = 0; mt < 4; ++mt) {
            const int row = m0 + wr * 64 + mt * 16 + (lane >> 2);
#pragma unroll
            for (int nt = 0; nt < 8; ++nt) {
                const int col = n0 + wc * 64 + nt * 8 + (lane & 3) * 2;
                const float b0 = bias[col], b1 = bias[col + 1];
                const float v0 = (acc[mt][nt][0] + b0) * scale;
                const float v1 = (acc[mt][nt][1] + b1) * scale;
                const float v2 = (acc[mt][nt][2] + b0) * scale;
                const float v3 = (acc[mt][nt][3] + b1) * scale;
                const size_t i0 = ((size_t)row << 10) + col;
                const size_t i1 = i0 + (8 << 10);
                __nv_bfloat16 h0, h1, h2, h3, l0, l1, l2, l3;
                bsplit(v0, h0, l0); bsplit(v1, h1, l1);
                bsplit(v2, h2, l2); bsplit(v3, h3, l3);
                *(__nv_bfloat162*)(Chi + i0) = __halves2bfloat162(h0, h1);
                *(__nv_bfloat162*)(Clo + i0) = __halves2bfloat162(l0, l1);
                *(__nv_bfloat162*)(Chi + i1) = __halves2bfloat162(h2, h3);
                *(__nv_bfloat162*)(Clo + i1) = __halves2bfloat162(l2, l3);
            }
        }
    } else {
        // V region: bias + transpose through smem -> head-major Vt bf16.
        float* ts = (float*)dynsm;   // 128 x 128 fp32, stride 130
#pragma unroll
        for (int mt = 0; mt < 4; ++mt) {
            const int rl = wr * 64 + mt * 16 + (lane >> 2);
#pragma unroll
            for (int nt = 0; nt < 8; ++nt) {
                const int cl = wc * 64 + nt * 8 + (lane & 3) * 2;
                const float b0 = bias[n0 + cl], b1 = bias[n0 + cl + 1];
                ts[rl * 130 + cl]           = acc[mt][nt][0] + b0;
                ts[rl * 130 + cl + 1]       = acc[mt][nt][1] + b1;
                ts[(rl + 8) * 130 + cl]     = acc[mt][nt][2] + b0;
                ts[(rl + 8) * 130 + cl + 1] = acc[mt][nt][3] + b1;
            }
        }
        __syncthreads();
        const int bb = m0 >> 10;
        const int k0 = m0 & 1023;
        __nv_bfloat16* dst = vt + (((size_t)(bb * 1024 + n0 + tid)) << 10) + k0;
#pragma unroll
        for (int k = 0; k < 128; k += 8) {
            __nv_bfloat162 p0 = __halves2bfloat162(
                __float2bfloat16(ts[(k + 0) * 130 + tid]),
                __float2bfloat16(ts[(k + 1) * 130 + tid]));
            __nv_bfloat162 p1 = __halves2bfloat162(
                __float2bfloat16(ts[(k + 2) * 130 + tid]),
                __float2bfloat16(ts[(k + 3) * 130 + tid]));
            __nv_bfloat162 p2 = __halves2bfloat162(
                __float2bfloat16(ts[(k + 4) * 130 + tid]),
                __float2bfloat16(ts[(k + 5) * 130 + tid]));
            __nv_bfloat162 p3 = __halves2bfloat162(
                __float2bfloat16(ts[(k + 6) * 130 + tid]),
                __float2bfloat16(ts[(k + 7) * 130 + tid]));
            uint4 pk;
            pk.x = *(uint32_t*)&p0; pk.y = *(uint32_t*)&p1;
            pk.z = *(uint32_t*)&p2; pk.w = *(uint32_t*)&p3;
            *(uint4*)(dst + k) = pk;
        }
    }
}

// ---------------------------------------------------------------------------
// HMMA GEMM template.
// SCORES=true: epilogue writes int16 S (x S_SCALE), bf16 P=exp(s), and a
//   deterministic per-(row, nblock) rowsum partial (smem reduce, no atomics).
// SCORES=false: fp32 output (out-proj).
// ---------------------------------------------------------------------------
template<int KCH, int PARTS, bool SCORES>
__global__ void __launch_bounds__(128, 2) gemm64(
    const __nv_bfloat16* __restrict__ Ahi, const __nv_bfloat16* __restrict__ Alo,
    const __nv_bfloat16* __restrict__ Bhi, const __nv_bfloat16* __restrict__ Blo,
    const float* __restrict__ bias, float* __restrict__ Cf,
    short* __restrict__ Cs, __nv_bfloat16* __restrict__ Pe,
    float* __restrict__ part, float scale,
    long sA0, long sA1, long sB0, long sB1, long sC0, long sC1)
{
    extern __shared__ __align__(16) char dynsm[];
    const uint32_t smBase = smem_u32(dynsm);

    const int tid  = threadIdx.x;
    const int lane = tid & 31;
    const int wid  = tid >> 5;
    const int wr   = wid >> 1;
    const int wc   = wid & 1;
    const int z    = blockIdx.z;
    const int m0   = blockIdx.y * 128;
    const int n0   = blockIdx.x * 128;
    const size_t aOff = (size_t)(z >> 4) * sA0 + (size_t)(z & 15) * sA1;
    const size_t bOff = (size_t)(z >> 4) * sB0 + (size_t)(z & 15) * sB1;
    const size_t cOff = (size_t)(z >> 4) * sC0 + (size_t)(z & 15) * sC1;

    const int rA  = lane & 15;
    const int cAh = lane >> 4;
    const int rBl = (lane & 7) + ((lane & 16) >> 1);
    const int cBh = (lane >> 3) & 1;

    float acc[4][8][4];
#pragma unroll
    for (int mt = 0; mt < 4; ++mt)
#pragma unroll
        for (int nt = 0; nt < 8; ++nt)
#pragma unroll
            for (int j = 0; j < 4; ++j) acc[mt][nt][j] = 0.f;

    auto prefetch = [&](int it, int stage) {
        const int part_ = it / KCH;
        const int ko    = (it % KCH) << 6;
        const __nv_bfloat16* Ap = (PARTS == 3 && part_ == 2) ? Alo : Ahi;
        const __nv_bfloat16* Bp = (PARTS == 3 && part_ == 1) ? Blo : Bhi;
        const uint32_t as = smBase + (uint32_t)stage * 32768u;
        const uint32_t bs = as + 16384u;
#pragma unroll
        for (int i = 0; i < 8; ++i) {
            int q = i * 128 + tid;
            int r = q >> 3, c = q & 7;
            CP_ASYNC16(as + sw128(r, c),
                       Ap + aOff + (((size_t)(m0 + r)) << 10) + ko + c * 8);
            CP_ASYNC16(bs + sw128(r, c),
                       Bp + bOff + (((size_t)(n0 + r)) << 10) + ko + c * 8);
        }
        CP_COMMIT();
    };

    const int NIT = PARTS * KCH;
    prefetch(0, 0);
    if (NIT > 1) prefetch(1, 1);

    for (int it = 0; it < NIT; ++it) {
        CP_WAIT1();
        __syncthreads();
        if (it + 2 < NIT) prefetch(it + 2, (it + 2) % 3);
        else CP_COMMIT();

        const uint32_t aT = smBase + (uint32_t)(it % 3) * 32768u;
        const uint32_t bT = aT + 16384u;

#pragma unroll
        for (int ks = 0; ks < 4; ++ks) {
            uint32_t af[4][4];
            uint32_t bf[8][2];
#pragma unroll
            for (int mt = 0; mt < 4; ++mt) {
                int r = wr * 64 + mt * 16 + rA;
                ldsm4(af[mt][0], af[mt][1], af[mt][2], af[mt][3],
                      aT + sw128(r, ks * 2 + cAh));
            }
#pragma unroll
            for (int tp = 0; tp < 4; ++tp) {
                int r = wc * 64 + tp * 16 + rBl;
                uint32_t x0, x1, x2, x3;
                ldsm4(x0, x1, x2, x3, bT + sw128(r, ks * 2 + cBh));
                bf[tp * 2][0] = x0;     bf[tp * 2][1] = x1;
                bf[tp * 2 + 1][0] = x2; bf[tp * 2 + 1][1] = x3;
            }
#pragma unroll
            for (int mt = 0; mt < 4; ++mt)
#pragma unroll
                for (int nt = 0; nt < 8; ++nt)
                    mma_bf16(acc[mt][nt], af[mt], bf[nt]);
        }
    }
    __syncthreads();   // mainloop smem dead beyond this point

    if (SCORES) {
        float* prt = (float*)dynsm;   // [128][8] row partials
        const int cidx = wc * 4 + (lane & 3);
#pragma unroll
        for (int mt = 0; mt < 4; ++mt) {
            const int rl  = wr * 64 + mt * 16 + (lane >> 2);
            const int row = m0 + rl;
            float ra0 = 0.f, ra1 = 0.f;
#pragma unroll
            for (int nt = 0; nt < 8; ++nt) {
                const int col = n0 + wc * 64 + nt * 8 + (lane & 3) * 2;
                const float s0 = acc[mt][nt][0];
                const float s1 = acc[mt][nt][1];
                const float s2 = acc[mt][nt][2];
                const float s3 = acc[mt][nt][3];
                const size_t i0 = cOff + ((size_t)row << 10) + col;
                const size_t i1 = i0 + (8 << 10);
                *(short2*)(Cs + i0) = make_short2(squant(s0 * S_SCALE),
                                                  squant(s1 * S_SCALE));
                *(short2*)(Cs + i1) = make_short2(squant(s2 * S_SCALE),
                                                  squant(s3 * S_SCALE));
                const float e0 = __expf(s0), e1 = __expf(s1);
                const float e2 = __expf(s2), e3 = __expf(s3);
                ra0 += e0 + e1;
                ra1 += e2 + e3;
                *(__nv_bfloat162*)(Pe + i0) =
                    __halves2bfloat162(__float2bfloat16(e0), __float2bfloat16(e1));
                *(__nv_bfloat162*)(Pe + i1) =
                    __halves2bfloat162(__float2bfloat16(e2), __float2bfloat16(e3));
            }
            prt[rl * 8 + cidx]       = ra0;
            prt[(rl + 8) * 8 + cidx] = ra1;
        }
        __syncthreads();
        // one partial per row per n-block, deterministic order
        {
            float s = 0.f;
#pragma unroll
            for (int c = 0; c < 8; ++c) s += prt[tid * 8 + c];
            part[(size_t)blockIdx.x * PART_STRIDE + (size_t)z * 512 + m0 + tid] = s;
        }
    } else {
#pragma unroll
        for (int mt = 0; mt < 4; ++mt) {
            const int row = m0 + wr * 64 + mt * 16 + (lane >> 2);
#pragma unroll
            for (int nt = 0; nt < 8; ++nt) {
                const int col = n0 + wc * 64 + nt * 8 + (lane & 3) * 2;
                const float b0 = bias ? bias[col]     : 0.f;
                const float b1 = bias ? bias[col + 1] : 0.f;
                const size_t i0 = cOff + ((size_t)row << 10) + col;
                const size_t i1 = i0 + (8 << 10);
                Cf[i0]     = (acc[mt][nt][0] + b0) * scale;
                Cf[i0 + 1] = (acc[mt][nt][1] + b1) * scale;
                Cf[i1]     = (acc[mt][nt][2] + b0) * scale;
                Cf[i1 + 1] = (acc[mt][nt][3] + b1) * scale;
            }
        }
    }
}

// ---------------------------------------------------------------------------
// Pure ctx GEMM: per z=(b,h)  ctx[512,64] = P[512,1024] @ Vt[64,1024]^T.
// Block 128x64 (4 warps, warp tile 64x32), BK=64, NIT=16, 3-stage cp.async.
// Epilogue normalizes by 1/rowsum (sum of 8 deterministic partials).
// SMEM: 3 x (A 16KB + B 8KB) = 72KB.
// ---------------------------------------------------------------------------
__global__ void __launch_bounds__(128, 2) ctx_pure(
    const __nv_bfloat16* __restrict__ P,
    const __nv_bfloat16* __restrict__ Vt,
    const float* __restrict__ part,
    __nv_bfloat16* __restrict__ Chi)
{
    extern __shared__ __align__(16) char dynsm[];
    const uint32_t smBase = smem_u32(dynsm);

    const int tid  = threadIdx.x;
    const int lane = tid & 31;
    const int wid  = tid >> 5;
    const int wr   = wid >> 1;   // 0..1 (64 rows)
    const int wc   = wid & 1;    // 0..1 (32 cols)
    const int z    = blockIdx.z, b = z >> 4, h = z & 15;
    const int m0   = blockIdx.y * 128;
    const size_t pOff = ((size_t)z * 512 + m0) << 10;
    const size_t vOff = ((size_t)z * 64) << 10;

    const int rA  = lane & 15;
    const int cAh = lane >> 4;
    const int rBl = (lane & 7) + ((lane & 16) >> 1);
    const int cBh = (lane >> 3) & 1;

    float acc[4][4][4];
#pragma unroll
    for (int mt = 0; mt < 4; ++mt)
#pragma unroll
        for (int nt = 0; nt < 4; ++nt)
#pragma unroll
            for (int j = 0; j < 4; ++j) acc[mt][nt][j] = 0.f;

    auto prefetch = [&](int kc, int stage) {
        const int ko = kc << 6;
        const uint32_t as = smBase + (uint32_t)stage * 24576u;
        const uint32_t bs = as + 16384u;
#pragma unroll
        for (int i = 0; i < 8; ++i) {
            int q = i * 128 + tid;
            int r = q >> 3, c = q & 7;
            CP_ASYNC16(as + sw128(r, c),
                       P + pOff + (((size_t)r) << 10) + ko + c * 8);
        }
#pragma unroll
        for (int i = 0; i < 4; ++i) {
            int q = i * 128 + tid;
            int r = q >> 3, c = q & 7;
            CP_ASYNC16(bs + sw128(r, c),
                       Vt + vOff + (((size_t)r) << 10) + ko + c * 8);
        }
        CP_COMMIT();
    };

    const int NIT = 16;
    prefetch(0, 0);
    prefetch(1, 1);

    for (int it = 0; it < NIT; ++it) {
        CP_WAIT1();
        __syncthreads();
        if (it + 2 < NIT) prefetch(it + 2, (it + 2) % 3);
        else CP_COMMIT();

        const uint32_t aT = smBase + (uint32_t)(it % 3) * 24576u;
        const uint32_t bT = aT + 16384u;

#pragma unroll
        for (int ks = 0; ks < 4; ++ks) {
            uint32_t af[4][4];
            uint32_t bf[4][2];
#pragma unroll
            for (int mt = 0; mt < 4; ++mt) {
                int r = wr * 64 + mt * 16 + rA;
                ldsm4(af[mt][0], af[mt][1], af[mt][2], af[mt][3],
                      aT + sw128(r, ks * 2 + cAh));
            }
#pragma unroll
            for (int tp = 0; tp < 2; ++tp) {
                int r = wc * 32 + tp * 16 + rBl;
                uint32_t x0, x1, x2, x3;
                ldsm4(x0, x1, x2, x3, bT + sw128(r, ks * 2 + cBh));
                bf[tp * 2][0] = x0;     bf[tp * 2][1] = x1;
                bf[tp * 2 + 1][0] = x2; bf[tp * 2 + 1][1] = x3;
            }
#pragma unroll
            for (int mt = 0; mt < 4; ++mt)
#pragma unroll
                for (int nt = 0; nt < 4; ++nt)
                    mma_bf16(acc[mt][nt], af[mt], bf[nt]);
        }
    }
    __syncthreads();

    // per-row 1/rowsum into smem (deterministic 8-partial sum)
    float* rs = (float*)dynsm;
    {
        float s = 0.f;
        const float* pp = part + (size_t)z * 512 + m0 + tid;
#pragma unroll
        for (int x = 0; x < 8; ++x) s += pp[(size_t)x * PART_STRIDE];
        rs[tid] = 1.0f / s;
    }
    __syncthreads();

#pragma unroll
    for (int mt = 0; mt < 4; ++mt) {
        const int rl = wr * 64 + mt * 16 + (lane >> 2);
        const float inv0 = rs[rl];
        const float inv1 = rs[rl + 8];
        const int row = m0 + rl;
#pragma unroll
        for (int nt = 0; nt < 4; ++nt) {
            const int col = h * 64 + wc * 32 + nt * 8 + (lane & 3) * 2;
            const size_t i0 = (((size_t)(b * 512 + row)) << 10) + col;
            const size_t i1 = i0 + (8 << 10);
            *(__nv_bfloat162*)(Chi + i0) =
                __halves2bfloat162(__float2bfloat16(acc[mt][nt][0] * inv0),
                                   __float2bfloat16(acc[mt][nt][1] * inv0));
            *(__nv_bfloat162*)(Chi + i1) =
                __halves2bfloat162(__float2bfloat16(acc[mt][nt][2] * inv1),
                                   __float2bfloat16(acc[mt][nt][3] * inv1));
        }
    }
}

// ---------------------------------------------------------------------------
// Head-mean of softmax(S) using rowsum partials. One block (512 thr) per
// (b,q). Thread owns 8-wide k-slice x 4 heads; register accumulation.
// ---------------------------------------------------------------------------
__global__ void __launch_bounds__(512) mean_heads(const short* __restrict__ S,
                                                  const float* __restrict__ part,
                                                  float* __restrict__ mean_out)
{
    __shared__ float prt[4][1024];
    __shared__ float sinv[16];
    const int bq = blockIdx.x;
    const int b = bq >> 9, q = bq & 511;
    const int tid = threadIdx.x;
    const int hg = tid >> 7;
    const int kb = (tid & 127) * 8;

    if (tid < 16) {
        float s = 0.f;
        const float* pp = part + (size_t)(b * 16 + tid) * 512 + q;
#pragma unroll
        for (int x = 0; x < 8; ++x) s += pp[(size_t)x * PART_STRIDE];
        sinv[tid] = 1.0f / s;
    }
    __syncthreads();

    float macc[8];
#pragma unroll
    for (int j = 0; j < 8; ++j) macc[j] = 0.f;

#pragma unroll
    for (int i = 0; i < 4; ++i) {
        const int h = hg + i * 4;
        const float inv = sinv[h];
        int4 raw = __ldg((const int4*)(S + (((size_t)(b * 16 + h) * 512 + q) << 10) + kb));
        const uint32_t* u = (const uint32_t*)&raw;
#pragma unroll
        for (int j = 0; j < 4; ++j) {
            macc[j * 2 + 0] += __expf((float)((short)(u[j] & 0xFFFF)) * S_INVSC) * inv;
            macc[j * 2 + 1] += __expf((float)((short)(u[j] >> 16))    * S_INVSC) * inv;
        }
    }
    *(float4*)&prt[hg][kb]     = make_float4(macc[0], macc[1], macc[2], macc[3]);
    *(float4*)&prt[hg][kb + 4] = make_float4(macc[4], macc[5], macc[6], macc[7]);
    __syncthreads();

    const float inv16 = 1.0f / HH_;
    float* mo = mean_out + (((size_t)bq) << 10);
    float s0 = (prt[0][tid] + prt[1][tid]) + (prt[2][tid] + prt[3][tid]);
    float s1 = (prt[0][tid + 512] + prt[1][tid + 512]) +
               (prt[2][tid + 512] + prt[3][tid + 512]);
    mo[tid]       = s0 * inv16;
    mo[tid + 512] = s1 * inv16;
}

// ---------------------------------------------------------------------------
// out = LayerNorm(query + attn_out) * gamma + beta.  One block per row.
// ---------------------------------------------------------------------------
__global__ void residual_ln(const float* __restrict__ q, const float* __restrict__ ao,
                            const float* __restrict__ gamma, const float* __restrict__ beta,
                            float* __restrict__ out)
{
    __shared__ float red[8];
    __shared__ float bcast;
    const long row = blockIdx.x;
    const int tid = threadIdx.x;

    float4 qa = *(const float4*)&q [row * DD + tid * 4];
    float4 aa = *(const float4*)&ao[row * DD + tid * 4];
    float x0 = qa.x + aa.x, x1 = qa.y + aa.y, x2 = qa.z + aa.z, x3 = qa.w + aa.w;

    float s = (x0 + x1) + (x2 + x3);
#pragma unroll
    for (int o = 16; o; o >>= 1) s += __shfl_xor_sync(0xffffffffu, s, o);
    if ((tid & 31) == 0) red[tid >> 5] = s;
    __syncthreads();
    if (tid < 8) {
        s = red[tid];
#pragma unroll
        for (int o = 4; o; o >>= 1) s += __shfl_xor_sync(0xffu, s, o);
        if (tid == 0) bcast = s;
    }
    __syncthreads();
    const float mu = bcast * (1.0f / DD);

    float d0 = x0 - mu, d1 = x1 - mu, d2 = x2 - mu, d3 = x3 - mu;
    float sq = (d0 * d0 + d1 * d1) + (d2 * d2 + d3 * d3);
#pragma unroll
    for (int o = 16; o; o >>= 1) sq += __shfl_xor_sync(0xffffffffu, sq, o);
    __syncthreads();
    if ((tid & 31) == 0) red[tid >> 5] = sq;
    __syncthreads();
    if (tid < 8) {
        sq = red[tid];
#pragma unroll
        for (int o = 4; o; o >>= 1) sq += __shfl_xor_sync(0xffu, sq, o);
        if (tid == 0) bcast = sq;
    }
    __syncthreads();
    const float rstd = rsqrtf(bcast * (1.0f / DD) + LN_EPS);

    float4 g = *(const float4*)&gamma[tid * 4];
    float4 be = *(const float4*)&beta[tid * 4];
    float4 o4;
    o4.x = d0 * rstd * g.x + be.x;
    o4.y = d1 * rstd * g.y + be.y;
    o4.z = d2 * rstd * g.z + be.z;
    o4.w = d3 * rstd * g.w + be.w;
    *(float4*)&out[row * DD + tid * 4] = o4;
}

// ---------------------------------------------------------------------------
extern "C" void kernel_launch(void* const* d_in, const int* in_sizes, int n_in,
                              void* d_out, int out_size)
{
    const float* query = (const float*)d_in[0];
    const float* key_  = (const float*)d_in[1];
    const float* value = (const float*)d_in[2];
    const float* in_w  = (const float*)d_in[3];
    const float* in_b  = (const float*)d_in[4];
    const float* out_w = (const float*)d_in[5];
    const float* out_b = (const float*)d_in[6];
    const float* gamma = (const float*)d_in[7];
    const float* beta  = (const float*)d_in[8];
    float* out = (float*)d_out;

    short* Si;
    float *AO, *PT;
    __nv_bfloat16* Pe;
    cudaGetSymbolAddress((void**)&Si, g_S);
    cudaGetSymbolAddress((void**)&Pe, g_P);
    cudaGetSymbolAddress((void**)&PT, g_part);
    cudaGetSymbolAddress((void**)&AO, g_AO);

    __nv_bfloat16 *qh, *ql, *kh, *kl, *vh, *vt, *wh, *wl, *woh;
    __nv_bfloat16 *qh2, *ql2, *kh2, *kl2, *ch;
    cudaGetSymbolAddress((void**)&qh,  g_qh);  cudaGetSymbolAddress((void**)&ql,  g_ql);
    cudaGetSymbolAddress((void**)&kh,  g_kh);  cudaGetSymbolAddress((void**)&kl,  g_kl);
    cudaGetSymbolAddress((void**)&vh,  g_vh);  cudaGetSymbolAddress((void**)&vt,  g_vt);
    cudaGetSymbolAddress((void**)&wh,  g_wh);  cudaGetSymbolAddress((void**)&wl,  g_wl);
    cudaGetSymbolAddress((void**)&woh, g_woh);
    cudaGetSymbolAddress((void**)&qh2, g_qh2); cudaGetSymbolAddress((void**)&ql2, g_ql2);
    cudaGetSymbolAddress((void**)&kh2, g_kh2); cudaGetSymbolAddress((void**)&kl2, g_kl2);
    cudaGetSymbolAddress((void**)&ch,  g_ch);

    // side stream + events (created once on the first, uncaptured call)
    static cudaStream_t s2 = nullptr;
    static cudaEvent_t evFork = nullptr, evJoin = nullptr;
    if (s2 == nullptr) {
        cudaStreamCreateWithFlags(&s2, cudaStreamNonBlocking);
        cudaEventCreateWithFlags(&evFork, cudaEventDisableTiming);
        cudaEventCreateWithFlags(&evJoin, cudaEventDisableTiming);
    }

    const int SM_G = 3 * 32768;
    const int SM_C = 3 * 24576;   // ctx_pure: 72 KB
    cudaFuncSetAttribute((const void*)qkv_proj,
                         cudaFuncAttributeMaxDynamicSharedMemorySize, SM_G);
    cudaFuncSetAttribute((const void*)gemm64<1, 3, true>,
                         cudaFuncAttributeMaxDynamicSharedMemorySize, SM_G);
    cudaFuncSetAttribute((const void*)gemm64<16, 1, false>,
                         cudaFuncAttributeMaxDynamicSharedMemorySize, SM_G);
    cudaFuncSetAttribute((const void*)ctx_pure,
                         cudaFuncAttributeMaxDynamicSharedMemorySize, SM_C);

    const float qscale = 0.125f;

    // 1) split everything in one launch
    {
        const long total4 = (long)BB*LQ*DD/4 + 2L*BB*LKV*DD/4 + 3L*DD*DD/4 + (long)DD*DD/4;
        split_all<<<(unsigned)((total4 + 255) / 256), 256>>>(
            (const float4*)query, (const float4*)key_, (const float4*)value,
            (const float4*)in_w, (const float4*)out_w,
            (__nv_bfloat162*)qh, (__nv_bfloat162*)ql,
            (__nv_bfloat162*)kh, (__nv_bfloat162*)kl,
            (__nv_bfloat162*)vh,
            (__nv_bfloat162*)wh, (__nv_bfloat162*)wl,
            (__nv_bfloat162*)woh);
    }

    // 2) merged Q/K/V projection (+ fused V transpose -> vt)
    qkv_proj<<<dim3(8, 160), 128, SM_G>>>(
        qh, ql, kh, kl, vh, wh, wl, in_b,
        qh2, ql2, kh2, kl2, vt, qscale);

    // 3) scores (bf16x3) -> int16 S + bf16 P=exp(s) + rowsum partials
    gemm64<1, 3, true><<<dim3(8, 4, BB * HH_), 128, SM_G>>>(
        qh2, ql2, kh2, kl2, nullptr, nullptr, Si, Pe, PT, S_SCALE,
        (long)LQ * DD,  (long)HD,
        (long)LKV * DD, (long)HD,
        (long)HH_ * LQ * LKV, (long)LQ * LKV);

    // 4) pure ctx GEMM (P @ Vt^T), normalized in epilogue -> bf16 ch
    ctx_pure<<<dim3(1, 4, BB * HH_), 128, SM_C>>>(Pe, vt, PT, ch);

    // --- fork: mean_heads independent of out-proj/LN (disjoint d_out) ---
    cudaEventRecord(evFork, 0);
    cudaStreamWaitEvent(s2, evFork, 0);

    // 5a) side stream: head-mean of softmax -> attn_weights half of d_out
    mean_heads<<<BB * LQ, 512, 0, s2>>>(Si, PT, out + (long)BB * LQ * DD);
    cudaEventRecord(evJoin, s2);

    // 5b) main stream: out projection (bf16x1) -> fp32 AO
    gemm64<16, 1, false><<<dim3(8, 32, 1), 128, SM_G>>>(
        ch, nullptr, woh, nullptr, out_b, AO, nullptr, nullptr, nullptr,
        1.0f, 0,0, 0,0, 0,0);

    // 6) residual + LayerNorm -> output half of d_out
    residual_ln<<<BB * LQ, 256>>>(query, AO, gamma, beta, out);

    // --- join ---
    cudaStreamWaitEvent(0, evJoin, 0);
}

// round 16
// speedup vs baseline: 1.0618x; 1.0618x over previous
#include <cuda_runtime.h>
#include <cuda_bf16.h>
#include <math.h>
#include <stdint.h>

// Problem constants
#define BB   8
#define LQ   512
#define LKV  1024
#define DD   1024
#define HH_  16
#define HD   64
#define LN_EPS 1e-5f

#define S_SCALE   4096.0f
#define S_INVSC   (1.0f / 4096.0f)
#define S_E2SC    (1.44269504088896340736f / 4096.0f)   // log2(e)/4096 (folded)

// ---------------------------------------------------------------------------
// Scratch (device globals: allocation-free per harness rules)
// ---------------------------------------------------------------------------
__device__ __align__(16) short g_S[(size_t)BB * HH_ * LQ * LKV]; // int16 scores (x4096)
__device__ float g_AO  [BB * LQ  * DD];              // fp32 attn_out
__device__ float g_rsum[BB * HH_ * LQ];              // 1/rowsum (from ctx_fused)

// bf16 buffers
__device__ __align__(16) __nv_bfloat16 g_qh [BB * LQ  * DD], g_ql [BB * LQ  * DD];
__device__ __align__(16) __nv_bfloat16 g_kh [BB * LKV * DD], g_kl [BB * LKV * DD];
__device__ __align__(16) __nv_bfloat16 g_vh [BB * LKV * DD];   // value input hi
__device__ __align__(16) __nv_bfloat16 g_vt [BB * LKV * DD];   // Vt head-major bf16
__device__ __align__(16) __nv_bfloat16 g_wh [3 * DD * DD],   g_wl [3 * DD * DD];
__device__ __align__(16) __nv_bfloat16 g_woh[DD * DD];
__device__ __align__(16) __nv_bfloat16 g_qh2[BB * LQ  * DD], g_ql2[BB * LQ  * DD];
__device__ __align__(16) __nv_bfloat16 g_kh2[BB * LKV * DD], g_kl2[BB * LKV * DD];
__device__ __align__(16) __nv_bfloat16 g_ch [BB * LQ  * DD];

// ---------------------------------------------------------------------------
// Baseline-PTX tensor-core helpers (NO tcgen05 — compute_103 target!)
// ---------------------------------------------------------------------------
__device__ __forceinline__ uint32_t smem_u32(const void* p) {
    uint32_t a;
    asm("{ .reg .u64 t; cvta.to.shared.u64 t, %1; cvt.u32.u64 %0, t; }" : "=r"(a) : "l"(p));
    return a;
}
__device__ __forceinline__ void ldsm4(uint32_t& r0, uint32_t& r1, uint32_t& r2,
                                      uint32_t& r3, uint32_t a) {
    asm volatile("ldmatrix.sync.aligned.m8n8.x4.shared.b16 {%0,%1,%2,%3}, [%4];"
                 : "=r"(r0), "=r"(r1), "=r"(r2), "=r"(r3) : "r"(a));
}
__device__ __forceinline__ void mma_bf16(float* d, const uint32_t* a, const uint32_t* b) {
    asm volatile("mma.sync.aligned.m16n8k16.row.col.f32.bf16.bf16.f32 "
                 "{%0,%1,%2,%3},{%4,%5,%6,%7},{%8,%9},{%0,%1,%2,%3};"
                 : "+f"(d[0]), "+f"(d[1]), "+f"(d[2]), "+f"(d[3])
                 : "r"(a[0]), "r"(a[1]), "r"(a[2]), "r"(a[3]), "r"(b[0]), "r"(b[1]));
}
#define CP_ASYNC16(s, g) \
    asm volatile("cp.async.cg.shared.global [%0], [%1], 16;" :: "r"(s), "l"(g))
#define CP_COMMIT() asm volatile("cp.async.commit_group;" ::: "memory")
#define CP_WAIT1()  asm volatile("cp.async.wait_group 1;"  ::: "memory")

// 128B-row XOR swizzle: 16B chunk c (0..7), row r
__device__ __forceinline__ uint32_t sw128(int r, int c) {
    return (uint32_t)(r * 128 + ((c ^ (r & 7)) << 4));
}
__device__ __forceinline__ void bsplit(float v, __nv_bfloat16& h, __nv_bfloat16& l) {
    h = __float2bfloat16(v);
    l = __float2bfloat16(v - __bfloat162float(h));
}
__device__ __forceinline__ short squant(float v) {
    v = fminf(fmaxf(v, -32700.f), 32700.f);
    return (short)__float2int_rn(v);
}

// ---------------------------------------------------------------------------
// One launch: split all inputs/weights (hi/lo or hi-only per segment)
// ---------------------------------------------------------------------------
__device__ __forceinline__ void seg_split2(float4 v, __nv_bfloat162* hi,
                                           __nv_bfloat162* lo, long i) {
    __nv_bfloat16 h0, h1, h2, h3, l0, l1, l2, l3;
    bsplit(v.x, h0, l0); bsplit(v.y, h1, l1);
    bsplit(v.z, h2, l2); bsplit(v.w, h3, l3);
    hi[i * 2 + 0] = __halves2bfloat162(h0, h1);
    hi[i * 2 + 1] = __halves2bfloat162(h2, h3);
    lo[i * 2 + 0] = __halves2bfloat162(l0, l1);
    lo[i * 2 + 1] = __halves2bfloat162(l2, l3);
}
__device__ __forceinline__ void seg_split1(float4 v, __nv_bfloat162* hi, long i) {
    hi[i * 2 + 0] = __halves2bfloat162(__float2bfloat16(v.x), __float2bfloat16(v.y));
    hi[i * 2 + 1] = __halves2bfloat162(__float2bfloat16(v.z), __float2bfloat16(v.w));
}

__global__ void split_all(const float4* __restrict__ q, const float4* __restrict__ k,
                          const float4* __restrict__ v, const float4* __restrict__ w,
                          const float4* __restrict__ wo,
                          __nv_bfloat162* qh, __nv_bfloat162* ql,
                          __nv_bfloat162* kh, __nv_bfloat162* kl,
                          __nv_bfloat162* vh,
                          __nv_bfloat162* wh, __nv_bfloat162* wl,
                          __nv_bfloat162* woh)
{
    const long N1 = (long)BB * LQ * DD / 4;
    const long N2 = N1 + (long)BB * LKV * DD / 4;
    const long N3 = N2 + (long)BB * LKV * DD / 4;
    const long N4 = N3 + 3L * DD * DD / 4;
    const long N5 = N4 + (long)DD * DD / 4;
    long i = (long)blockIdx.x * blockDim.x + threadIdx.x;
    if (i < N1)      seg_split2(q[i], qh, ql, i);
    else if (i < N2) { i -= N1; seg_split2(k[i], kh, kl, i); }
    else if (i < N3) { i -= N2; seg_split1(v[i], vh, i); }
    else if (i < N4) { i -= N3; seg_split2(w[i], wh, wl, i); }
    else if (i < N5) { i -= N4; seg_split1(wo[i], woh, i); }
}

// ---------------------------------------------------------------------------
// Merged Q/K/V projection. Grid (8, 160): y<32 Q, y<96 K, else V.
// ---------------------------------------------------------------------------
__global__ void __launch_bounds__(128, 2) qkv_proj(
    const __nv_bfloat16* __restrict__ qhp, const __nv_bfloat16* __restrict__ qlp,
    const __nv_bfloat16* __restrict__ khp, const __nv_bfloat16* __restrict__ klp,
    const __nv_bfloat16* __restrict__ vhp,
    const __nv_bfloat16* __restrict__ whp, const __nv_bfloat16* __restrict__ wlp,
    const float* __restrict__ in_b,
    __nv_bfloat16* __restrict__ qh2, __nv_bfloat16* __restrict__ ql2,
    __nv_bfloat16* __restrict__ kh2, __nv_bfloat16* __restrict__ kl2,
    __nv_bfloat16* __restrict__ vt, float qscale)
{
    extern __shared__ __align__(16) char dynsm[];
    const uint32_t smBase = smem_u32(dynsm);

    const int tid  = threadIdx.x;
    const int lane = tid & 31;
    const int wid  = tid >> 5;
    const int wr   = wid >> 1;
    const int wc   = wid & 1;
    const int y    = blockIdx.y;
    const int n0   = blockIdx.x * 128;

    int region, m0, NIT;
    float scale = 1.0f;
    const __nv_bfloat16 *Ahi, *Alo, *Bhi, *Blo;
    const float* bias;
    if (y < 32) {
        region = 0; m0 = y * 128; NIT = 48; scale = qscale;
        Ahi = qhp; Alo = qlp; Bhi = whp; Blo = wlp; bias = in_b;
    } else if (y < 96) {
        region = 1; m0 = (y - 32) * 128; NIT = 48;
        Ahi = khp; Alo = klp;
        Bhi = whp + (size_t)DD * DD; Blo = wlp + (size_t)DD * DD;
        bias = in_b + DD;
    } else {
        region = 2; m0 = (y - 96) * 128; NIT = 16;
        Ahi = vhp; Alo = vhp;
        Bhi = whp + 2ul * DD * DD; Blo = Bhi;
        bias = in_b + 2 * DD;
    }

    const int rA  = lane & 15;
    const int cAh = lane >> 4;
    const int rBl = (lane & 7) + ((lane & 16) >> 1);
    const int cBh = (lane >> 3) & 1;

    float acc[4][8][4];
#pragma unroll
    for (int mt = 0; mt < 4; ++mt)
#pragma unroll
        for (int nt = 0; nt < 8; ++nt)
#pragma unroll
            for (int j = 0; j < 4; ++j) acc[mt][nt][j] = 0.f;

    auto prefetch = [&](int it, int stage) {
        const int part = it >> 4;
        const int ko   = (it & 15) << 6;
        const __nv_bfloat16* Ap = (part == 2) ? Alo : Ahi;
        const __nv_bfloat16* Bp = (part == 1) ? Blo : Bhi;
        const uint32_t as = smBase + (uint32_t)stage * 32768u;
        const uint32_t bs = as + 16384u;
#pragma unroll
        for (int i = 0; i < 8; ++i) {
            int q = i * 128 + tid;
            int r = q >> 3, c = q & 7;
            CP_ASYNC16(as + sw128(r, c),
                       Ap + (((size_t)(m0 + r)) << 10) + ko + c * 8);
            CP_ASYNC16(bs + sw128(r, c),
                       Bp + (((size_t)(n0 + r)) << 10) + ko + c * 8);
        }
        CP_COMMIT();
    };

    prefetch(0, 0);
    prefetch(1, 1);

    for (int it = 0; it < NIT; ++it) {
        CP_WAIT1();
        __syncthreads();
        if (it + 2 < NIT) prefetch(it + 2, (it + 2) % 3);
        else CP_COMMIT();

        const uint32_t aT = smBase + (uint32_t)(it % 3) * 32768u;
        const uint32_t bT = aT + 16384u;

#pragma unroll
        for (int ks = 0; ks < 4; ++ks) {
            uint32_t af[4][4];
            uint32_t bf[8][2];
#pragma unroll
            for (int mt = 0; mt < 4; ++mt) {
                int r = wr * 64 + mt * 16 + rA;
                ldsm4(af[mt][0], af[mt][1], af[mt][2], af[mt][3],
                      aT + sw128(r, ks * 2 + cAh));
            }
#pragma unroll
            for (int tp = 0; tp < 4; ++tp) {
                int r = wc * 64 + tp * 16 + rBl;
                uint32_t x0, x1, x2, x3;
                ldsm4(x0, x1, x2, x3, bT + sw128(r, ks * 2 + cBh));
                bf[tp * 2][0] = x0;     bf[tp * 2][1] = x1;
                bf[tp * 2 + 1][0] = x2; bf[tp * 2 + 1][1] = x3;
            }
#pragma unroll
            for (int mt = 0; mt < 4; ++mt)
#pragma unroll
                for (int nt = 0; nt < 8; ++nt)
                    mma_bf16(acc[mt][nt], af[mt], bf[nt]);
        }
    }
    __syncthreads();

    if (region < 2) {
        __nv_bfloat16* Chi = region ? kh2 : qh2;
        __nv_bfloat16* Clo = region ? kl2 : ql2;
#pragma unroll
        for (int mt = 0; mt < 4; ++mt) {
            const int row = m0 + wr * 64 + mt * 16 + (lane >> 2);
#pragma unroll
            for (int nt = 0; nt < 8; ++nt) {
                const int col = n0 + wc * 64 + nt * 8 + (lane & 3) * 2;
                const float b0 = bias[col], b1 = bias[col + 1];
                const float v0 = (acc[mt][nt][0] + b0) * scale;
                const float v1 = (acc[mt][nt][1] + b1) * scale;
                const float v2 = (acc[mt][nt][2] + b0) * scale;
                const float v3 = (acc[mt][nt][3] + b1) * scale;
                const size_t i0 = ((size_t)row << 10) + col;
                const size_t i1 = i0 + (8 << 10);
                __nv_bfloat16 h0, h1, h2, h3, l0, l1, l2, l3;
                bsplit(v0, h0, l0); bsplit(v1, h1, l1);
                bsplit(v2, h2, l2); bsplit(v3, h3, l3);
                *(__nv_bfloat162*)(Chi + i0) = __halves2bfloat162(h0, h1);
                *(__nv_bfloat162*)(Clo + i0) = __halves2bfloat162(l0, l1);
                *(__nv_bfloat162*)(Chi + i1) = __halves2bfloat162(h2, h3);
                *(__nv_bfloat162*)(Clo + i1) = __halves2bfloat162(l2, l3);
            }
        }
    } else {
        // V region: bias + transpose through smem -> head-major Vt bf16.
        float* ts = (float*)dynsm;   // 128 x 128 fp32, stride 130
#pragma unroll
        for (int mt = 0; mt < 4; ++mt) {
            const int rl = wr * 64 + mt * 16 + (lane >> 2);
#pragma unroll
            for (int nt = 0; nt < 8; ++nt) {
                const int cl = wc * 64 + nt * 8 + (lane & 3) * 2;
                const float b0 = bias[n0 + cl], b1 = bias[n0 + cl + 1];
                ts[rl * 130 + cl]           = acc[mt][nt][0] + b0;
                ts[rl * 130 + cl + 1]       = acc[mt][nt][1] + b1;
                ts[(rl + 8) * 130 + cl]     = acc[mt][nt][2] + b0;
                ts[(rl + 8) * 130 + cl + 1] = acc[mt][nt][3] + b1;
            }
        }
        __syncthreads();
        const int bb = m0 >> 10;
        const int k0 = m0 & 1023;
        __nv_bfloat16* dst = vt + (((size_t)(bb * 1024 + n0 + tid)) << 10) + k0;
#pragma unroll
        for (int k = 0; k < 128; k += 8) {
            __nv_bfloat162 p0 = __halves2bfloat162(
                __float2bfloat16(ts[(k + 0) * 130 + tid]),
                __float2bfloat16(ts[(k + 1) * 130 + tid]));
            __nv_bfloat162 p1 = __halves2bfloat162(
                __float2bfloat16(ts[(k + 2) * 130 + tid]),
                __float2bfloat16(ts[(k + 3) * 130 + tid]));
            __nv_bfloat162 p2 = __halves2bfloat162(
                __float2bfloat16(ts[(k + 4) * 130 + tid]),
                __float2bfloat16(ts[(k + 5) * 130 + tid]));
            __nv_bfloat162 p3 = __halves2bfloat162(
                __float2bfloat16(ts[(k + 6) * 130 + tid]),
                __float2bfloat16(ts[(k + 7) * 130 + tid]));
            uint4 pk;
            pk.x = *(uint32_t*)&p0; pk.y = *(uint32_t*)&p1;
            pk.z = *(uint32_t*)&p2; pk.w = *(uint32_t*)&p3;
            *(uint4*)(dst + k) = pk;
        }
    }
}

// ---------------------------------------------------------------------------
// HMMA GEMM template. I16OUT=true: quantize (acc+bias)*scale to int16 (scores).
// I16OUT=false: fp32 output (out-proj).
// ---------------------------------------------------------------------------
template<int KCH, int PARTS, bool I16OUT>
__global__ void __launch_bounds__(128, 2) gemm64(
    const __nv_bfloat16* __restrict__ Ahi, const __nv_bfloat16* __restrict__ Alo,
    const __nv_bfloat16* __restrict__ Bhi, const __nv_bfloat16* __restrict__ Blo,
    const float* __restrict__ bias, float* __restrict__ Cf,
    short* __restrict__ Cs, float scale,
    long sA0, long sA1, long sB0, long sB1, long sC0, long sC1)
{
    extern __shared__ __align__(16) char dynsm[];
    const uint32_t smBase = smem_u32(dynsm);

    const int tid  = threadIdx.x;
    const int lane = tid & 31;
    const int wid  = tid >> 5;
    const int wr   = wid >> 1;
    const int wc   = wid & 1;
    const int z    = blockIdx.z;
    const int m0   = blockIdx.y * 128;
    const int n0   = blockIdx.x * 128;
    const size_t aOff = (size_t)(z >> 4) * sA0 + (size_t)(z & 15) * sA1;
    const size_t bOff = (size_t)(z >> 4) * sB0 + (size_t)(z & 15) * sB1;
    const size_t cOff = (size_t)(z >> 4) * sC0 + (size_t)(z & 15) * sC1;

    const int rA  = lane & 15;
    const int cAh = lane >> 4;
    const int rBl = (lane & 7) + ((lane & 16) >> 1);
    const int cBh = (lane >> 3) & 1;

    float acc[4][8][4];
#pragma unroll
    for (int mt = 0; mt < 4; ++mt)
#pragma unroll
        for (int nt = 0; nt < 8; ++nt)
#pragma unroll
            for (int j = 0; j < 4; ++j) acc[mt][nt][j] = 0.f;

    auto prefetch = [&](int it, int stage) {
        const int part = it / KCH;
        const int ko   = (it % KCH) << 6;
        const __nv_bfloat16* Ap = (PARTS == 3 && part == 2) ? Alo : Ahi;
        const __nv_bfloat16* Bp = (PARTS == 3 && part == 1) ? Blo : Bhi;
        const uint32_t as = smBase + (uint32_t)stage * 32768u;
        const uint32_t bs = as + 16384u;
#pragma unroll
        for (int i = 0; i < 8; ++i) {
            int q = i * 128 + tid;
            int r = q >> 3, c = q & 7;
            CP_ASYNC16(as + sw128(r, c),
                       Ap + aOff + (((size_t)(m0 + r)) << 10) + ko + c * 8);
            CP_ASYNC16(bs + sw128(r, c),
                       Bp + bOff + (((size_t)(n0 + r)) << 10) + ko + c * 8);
        }
        CP_COMMIT();
    };

    const int NIT = PARTS * KCH;
    prefetch(0, 0);
    if (NIT > 1) prefetch(1, 1);

    for (int it = 0; it < NIT; ++it) {
        CP_WAIT1();
        __syncthreads();
        if (it + 2 < NIT) prefetch(it + 2, (it + 2) % 3);
        else CP_COMMIT();

        const uint32_t aT = smBase + (uint32_t)(it % 3) * 32768u;
        const uint32_t bT = aT + 16384u;

#pragma unroll
        for (int ks = 0; ks < 4; ++ks) {
            uint32_t af[4][4];
            uint32_t bf[8][2];
#pragma unroll
            for (int mt = 0; mt < 4; ++mt) {
                int r = wr * 64 + mt * 16 + rA;
                ldsm4(af[mt][0], af[mt][1], af[mt][2], af[mt][3],
                      aT + sw128(r, ks * 2 + cAh));
            }
#pragma unroll
            for (int tp = 0; tp < 4; ++tp) {
                int r = wc * 64 + tp * 16 + rBl;
                uint32_t x0, x1, x2, x3;
                ldsm4(x0, x1, x2, x3, bT + sw128(r, ks * 2 + cBh));
                bf[tp * 2][0] = x0;     bf[tp * 2][1] = x1;
                bf[tp * 2 + 1][0] = x2; bf[tp * 2 + 1][1] = x3;
            }
#pragma unroll
            for (int mt = 0; mt < 4; ++mt)
#pragma unroll
                for (int nt = 0; nt < 8; ++nt)
                    mma_bf16(acc[mt][nt], af[mt], bf[nt]);
        }
    }
    __syncthreads();

#pragma unroll
    for (int mt = 0; mt < 4; ++mt) {
        const int row = m0 + wr * 64 + mt * 16 + (lane >> 2);
#pragma unroll
        for (int nt = 0; nt < 8; ++nt) {
            const int col = n0 + wc * 64 + nt * 8 + (lane & 3) * 2;
            const float b0 = bias ? bias[col]     : 0.f;
            const float b1 = bias ? bias[col + 1] : 0.f;
            const float v0 = (acc[mt][nt][0] + b0) * scale;
            const float v1 = (acc[mt][nt][1] + b1) * scale;
            const float v2 = (acc[mt][nt][2] + b0) * scale;
            const float v3 = (acc[mt][nt][3] + b1) * scale;
            const size_t i0 = cOff + ((size_t)row << 10) + col;
            const size_t i1 = i0 + (8 << 10);
            if (I16OUT) {
                *(short2*)(Cs + i0) = make_short2(squant(v0), squant(v1));
                *(short2*)(Cs + i1) = make_short2(squant(v2), squant(v3));
            } else {
                Cf[i0] = v0; Cf[i0 + 1] = v1;
                Cf[i1] = v2; Cf[i1 + 1] = v3;
            }
        }
    }
}

// ---------------------------------------------------------------------------
// Head-mean of softmax(S) using precomputed 1/rowsum from ctx_fused.
// exp2f with folded constant (one fewer FMUL per element vs __expf chain).
// ---------------------------------------------------------------------------
__global__ void __launch_bounds__(512) mean_heads(const short* __restrict__ S,
                                                  const float* __restrict__ rinv,
                                                  float* __restrict__ mean_out)
{
    __shared__ float part[4][1024];
    __shared__ float sinv[16];
    const int bq = blockIdx.x;
    const int b = bq >> 9, q = bq & 511;
    const int tid = threadIdx.x;
    const int hg = tid >> 7;
    const int kb = (tid & 127) * 8;

    if (tid < 16) sinv[tid] = __ldg(&rinv[(size_t)(b * 16 + tid) * 512 + q]);
    __syncthreads();

    float macc[8];
#pragma unroll
    for (int j = 0; j < 8; ++j) macc[j] = 0.f;

#pragma unroll
    for (int i = 0; i < 4; ++i) {
        const int h = hg + i * 4;
        const float inv = sinv[h];
        int4 raw = __ldg((const int4*)(S + (((size_t)(b * 16 + h) * 512 + q) << 10) + kb));
        const uint32_t* u = (const uint32_t*)&raw;
#pragma unroll
        for (int j = 0; j < 4; ++j) {
            macc[j * 2 + 0] += exp2f((float)((short)(u[j] & 0xFFFF)) * S_E2SC) * inv;
            macc[j * 2 + 1] += exp2f((float)((short)(u[j] >> 16))    * S_E2SC) * inv;
        }
    }
    *(float4*)&part[hg][kb]     = make_float4(macc[0], macc[1], macc[2], macc[3]);
    *(float4*)&part[hg][kb + 4] = make_float4(macc[4], macc[5], macc[6], macc[7]);
    __syncthreads();

    const float inv16 = 1.0f / HH_;
    float* mo = mean_out + (((size_t)bq) << 10);
    float s0 = (part[0][tid] + part[1][tid]) + (part[2][tid] + part[3][tid]);
    float s1 = (part[0][tid + 512] + part[1][tid + 512]) +
               (part[2][tid + 512] + part[3][tid + 512]);
    mo[tid]       = s0 * inv16;
    mo[tid + 512] = s1 * inv16;
}

// ---------------------------------------------------------------------------
// Fused ctx (plain bf16), SELF-NORMALIZING, exports 1/rowsum to global.
// exp2f with folded constant in the conversion stream.
// ---------------------------------------------------------------------------
__global__ void __launch_bounds__(512) ctx_fused(
    const short* __restrict__ S,
    const __nv_bfloat16* __restrict__ Vhi,
    __nv_bfloat16* __restrict__ Chi, float* __restrict__ rinv_out)
{
    extern __shared__ __align__(16) char dynsm[];
    const uint32_t smBase = smem_u32(dynsm);
    float* rs = (float*)(dynsm + 32768 + 3 * 8192);   // [128] row sums

    const int tid  = threadIdx.x;
    const int lane = tid & 31;
    const int wid  = tid >> 5;
    const int wr   = wid >> 2;
    const int wc   = wid & 3;
    const int z    = blockIdx.z, b = z >> 4, h = z & 15;
    const int m0   = blockIdx.y * 128;
    const size_t sOff  = ((size_t)z * 512 + m0) << 10;
    const size_t vOff  = ((size_t)z * 64) << 10;

    const int rA  = lane & 15;
    const int cAh = lane >> 4;
    const int rBl = (lane & 7) + ((lane & 16) >> 1);
    const int cBh = (lane >> 3) & 1;

    float acc[2][2][4];
#pragma unroll
    for (int mt = 0; mt < 2; ++mt)
#pragma unroll
        for (int nt = 0; nt < 2; ++nt)
#pragma unroll
            for (int j = 0; j < 4; ++j) acc[mt][nt][j] = 0.f;

    float rsum0 = 0.f, rsum1 = 0.f;

    int4 sreg[2];
    auto ldS = [&](int kc) {
#pragma unroll
        for (int i = 0; i < 2; ++i) {
            int idx = i * 512 + tid;
            int row = idx >> 3, c8 = idx & 7;
            sreg[i] = __ldg((const int4*)(S + sOff + ((size_t)row << 10) +
                                          (kc << 6) + c8 * 8));
        }
    };
    auto cpV = [&](int kc) {
        const uint32_t vs = smBase + 32768u + (uint32_t)(kc % 3) * 8192u;
        int r = tid >> 3, c = tid & 7;
        CP_ASYNC16(vs + sw128(r, c), Vhi + vOff + ((size_t)r << 10) + (kc << 6) + c * 8);
        CP_COMMIT();
    };

    ldS(0);
    cpV(0);
    cpV(1);

    for (int kc = 0; kc < 16; ++kc) {
        const uint32_t pB = smBase + (uint32_t)(kc & 1) * 16384u;
#pragma unroll
        for (int i = 0; i < 2; ++i) {
            int idx = i * 512 + tid;
            int row = idx >> 3, c8 = idx & 7;
            const uint32_t* u = (const uint32_t*)&sreg[i];
            uint32_t packed[4];
            float esum = 0.f;
#pragma unroll
            for (int j = 0; j < 4; ++j) {
                float a = exp2f((float)((short)(u[j] & 0xFFFF)) * S_E2SC);
                float c = exp2f((float)((short)(u[j] >> 16))    * S_E2SC);
                esum += a + c;
                __nv_bfloat162 pp = __halves2bfloat162(__float2bfloat16(a),
                                                       __float2bfloat16(c));
                packed[j] = *(uint32_t*)&pp;
            }
            if (i == 0) rsum0 += esum; else rsum1 += esum;
            uint32_t off = sw128(row, c8);
            asm volatile("st.shared.v4.b32 [%0], {%1, %2, %3, %4};" ::
                         "r"(pB + off), "r"(packed[0]), "r"(packed[1]),
                         "r"(packed[2]), "r"(packed[3]) : "memory");
        }
        if (kc + 1 < 16) ldS(kc + 1);

        CP_WAIT1();
        __syncthreads();
        if (kc + 2 < 16) cpV(kc + 2);
        else CP_COMMIT();

        const uint32_t phT = smBase + (uint32_t)(kc & 1) * 16384u;
        const uint32_t vhT = smBase + 32768u + (uint32_t)(kc % 3) * 8192u;

#pragma unroll
        for (int ks = 0; ks < 4; ++ks) {
            uint32_t ah[2][4];
            uint32_t bh[2][2];
#pragma unroll
            for (int mt = 0; mt < 2; ++mt) {
                int r = wr * 32 + mt * 16 + rA;
                ldsm4(ah[mt][0], ah[mt][1], ah[mt][2], ah[mt][3],
                      phT + sw128(r, ks * 2 + cAh));
            }
            {
                int r = wc * 16 + rBl;
                uint32_t x0, x1, x2, x3;
                ldsm4(x0, x1, x2, x3, vhT + sw128(r, ks * 2 + cBh));
                bh[0][0] = x0; bh[0][1] = x1; bh[1][0] = x2; bh[1][1] = x3;
            }
#pragma unroll
            for (int mt = 0; mt < 2; ++mt)
#pragma unroll
                for (int nt = 0; nt < 2; ++nt)
                    mma_bf16(acc[mt][nt], ah[mt], bh[nt]);
        }
    }

    // combine row sums: octet shuffle, then smem
#pragma unroll
    for (int o = 1; o < 8; o <<= 1) {
        rsum0 += __shfl_xor_sync(0xffffffffu, rsum0, o);
        rsum1 += __shfl_xor_sync(0xffffffffu, rsum1, o);
    }
    if ((tid & 7) == 0) {
        rs[tid >> 3]        = rsum0;
        rs[(tid >> 3) + 64] = rsum1;
    }
    __syncthreads();

    // export 1/rowsum for mean_heads
    if (tid < 128)
        rinv_out[(size_t)z * 512 + m0 + tid] = 1.0f / rs[tid];

#pragma unroll
    for (int mt = 0; mt < 2; ++mt) {
        const int rl = wr * 32 + mt * 16 + (lane >> 2);
        const float inv0 = 1.0f / rs[rl];
        const float inv1 = 1.0f / rs[rl + 8];
        const int row = m0 + rl;
#pragma unroll
        for (int nt = 0; nt < 2; ++nt) {
            const int col = h * 64 + wc * 16 + nt * 8 + (lane & 3) * 2;
            const size_t i0 = (((size_t)(b * 512 + row)) << 10) + col;
            const size_t i1 = i0 + (8 << 10);
            *(__nv_bfloat162*)(Chi + i0) =
                __halves2bfloat162(__float2bfloat16(acc[mt][nt][0] * inv0),
                                   __float2bfloat16(acc[mt][nt][1] * inv0));
            *(__nv_bfloat162*)(Chi + i1) =
                __halves2bfloat162(__float2bfloat16(acc[mt][nt][2] * inv1),
                                   __float2bfloat16(acc[mt][nt][3] * inv1));
        }
    }
}

// ---------------------------------------------------------------------------
// out = LayerNorm(query + attn_out) * gamma + beta.  One block per row.
// ---------------------------------------------------------------------------
__global__ void residual_ln(const float* __restrict__ q, const float* __restrict__ ao,
                            const float* __restrict__ gamma, const float* __restrict__ beta,
                            float* __restrict__ out)
{
    __shared__ float red[8];
    __shared__ float bcast;
    const long row = blockIdx.x;
    const int tid = threadIdx.x;

    float4 qa = *(const float4*)&q [row * DD + tid * 4];
    float4 aa = *(const float4*)&ao[row * DD + tid * 4];
    float x0 = qa.x + aa.x, x1 = qa.y + aa.y, x2 = qa.z + aa.z, x3 = qa.w + aa.w;

    float s = (x0 + x1) + (x2 + x3);
#pragma unroll
    for (int o = 16; o; o >>= 1) s += __shfl_xor_sync(0xffffffffu, s, o);
    if ((tid & 31) == 0) red[tid >> 5] = s;
    __syncthreads();
    if (tid < 8) {
        s = red[tid];
#pragma unroll
        for (int o = 4; o; o >>= 1) s += __shfl_xor_sync(0xffu, s, o);
        if (tid == 0) bcast = s;
    }
    __syncthreads();
    const float mu = bcast * (1.0f / DD);

    float d0 = x0 - mu, d1 = x1 - mu, d2 = x2 - mu, d3 = x3 - mu;
    float sq = (d0 * d0 + d1 * d1) + (d2 * d2 + d3 * d3);
#pragma unroll
    for (int o = 16; o; o >>= 1) sq += __shfl_xor_sync(0xffffffffu, sq, o);
    __syncthreads();
    if ((tid & 31) == 0) red[tid >> 5] = sq;
    __syncthreads();
    if (tid < 8) {
        sq = red[tid];
#pragma unroll
        for (int o = 4; o; o >>= 1) sq += __shfl_xor_sync(0xffu, sq, o);
        if (tid == 0) bcast = sq;
    }
    __syncthreads();
    const float rstd = rsqrtf(bcast * (1.0f / DD) + LN_EPS);

    float4 g = *(const float4*)&gamma[tid * 4];
    float4 be = *(const float4*)&beta[tid * 4];
    float4 o4;
    o4.x = d0 * rstd * g.x + be.x;
    o4.y = d1 * rstd * g.y + be.y;
    o4.z = d2 * rstd * g.z + be.z;
    o4.w = d3 * rstd * g.w + be.w;
    *(float4*)&out[row * DD + tid * 4] = o4;
}

// ---------------------------------------------------------------------------
extern "C" void kernel_launch(void* const* d_in, const int* in_sizes, int n_in,
                              void* d_out, int out_size)
{
    const float* query = (const float*)d_in[0];
    const float* key_  = (const float*)d_in[1];
    const float* value = (const float*)d_in[2];
    const float* in_w  = (const float*)d_in[3];
    const float* in_b  = (const float*)d_in[4];
    const float* out_w = (const float*)d_in[5];
    const float* out_b = (const float*)d_in[6];
    const float* gamma = (const float*)d_in[7];
    const float* beta  = (const float*)d_in[8];
    float* out = (float*)d_out;

    short* Si;
    float *AO, *RI;
    cudaGetSymbolAddress((void**)&Si, g_S);
    cudaGetSymbolAddress((void**)&AO, g_AO);
    cudaGetSymbolAddress((void**)&RI, g_rsum);

    __nv_bfloat16 *qh, *ql, *kh, *kl, *vh, *vt, *wh, *wl, *woh;
    __nv_bfloat16 *qh2, *ql2, *kh2, *kl2, *ch;
    cudaGetSymbolAddress((void**)&qh,  g_qh);  cudaGetSymbolAddress((void**)&ql,  g_ql);
    cudaGetSymbolAddress((void**)&kh,  g_kh);  cudaGetSymbolAddress((void**)&kl,  g_kl);
    cudaGetSymbolAddress((void**)&vh,  g_vh);  cudaGetSymbolAddress((void**)&vt,  g_vt);
    cudaGetSymbolAddress((void**)&wh,  g_wh);  cudaGetSymbolAddress((void**)&wl,  g_wl);
    cudaGetSymbolAddress((void**)&woh, g_woh);
    cudaGetSymbolAddress((void**)&qh2, g_qh2); cudaGetSymbolAddress((void**)&ql2, g_ql2);
    cudaGetSymbolAddress((void**)&kh2, g_kh2); cudaGetSymbolAddress((void**)&kl2, g_kl2);
    cudaGetSymbolAddress((void**)&ch,  g_ch);

    const int SM_G = 3 * 32768;
    const int SM_X = 2 * 16384 + 3 * 8192 + 512;
    cudaFuncSetAttribute((const void*)qkv_proj,
                         cudaFuncAttributeMaxDynamicSharedMemorySize, SM_G);
    cudaFuncSetAttribute((const void*)gemm64<1, 3, true>,
                         cudaFuncAttributeMaxDynamicSharedMemorySize, SM_G);
    cudaFuncSetAttribute((const void*)gemm64<16, 1, false>,
                         cudaFuncAttributeMaxDynamicSharedMemorySize, SM_G);
    cudaFuncSetAttribute((const void*)ctx_fused,
                         cudaFuncAttributeMaxDynamicSharedMemorySize, SM_X);

    const float qscale = 0.125f;

    // 1) split everything in one launch
    {
        const long total4 = (long)BB*LQ*DD/4 + 2L*BB*LKV*DD/4 + 3L*DD*DD/4 + (long)DD*DD/4;
        split_all<<<(unsigned)((total4 + 255) / 256), 256>>>(
            (const float4*)query, (const float4*)key_, (const float4*)value,
            (const float4*)in_w, (const float4*)out_w,
            (__nv_bfloat162*)qh, (__nv_bfloat162*)ql,
            (__nv_bfloat162*)kh, (__nv_bfloat162*)kl,
            (__nv_bfloat162*)vh,
            (__nv_bfloat162*)wh, (__nv_bfloat162*)wl,
            (__nv_bfloat162*)woh);
    }

    // 2) merged Q/K/V projection (+ fused V transpose -> vt)
    qkv_proj<<<dim3(8, 160), 128, SM_G>>>(
        qh, ql, kh, kl, vh, wh, wl, in_b,
        qh2, ql2, kh2, kl2, vt, qscale);

    // 3) scores (bf16x3) -> int16 S (scaled by 4096)
    gemm64<1, 3, true><<<dim3(8, 4, BB * HH_), 128, SM_G>>>(
        qh2, ql2, kh2, kl2, nullptr, nullptr, Si, S_SCALE,
        (long)LQ * DD,  (long)HD,
        (long)LKV * DD, (long)HD,
        (long)HH_ * LQ * LKV, (long)LQ * LKV);

    // 4) fused self-normalizing ctx MMA; exports 1/rowsum
    ctx_fused<<<dim3(1, 4, BB * HH_), 512, SM_X>>>(Si, vt, ch, RI);

    // 5) head-mean of softmax using exported rowsums (register accumulation)
    mean_heads<<<BB * LQ, 512>>>(Si, RI, out + (long)BB * LQ * DD);

    // 6) out projection (bf16x1) -> fp32 AO
    gemm64<16, 1, false><<<dim3(8, 32, 1), 128, SM_G>>>(
        ch, nullptr, woh, nullptr, out_b, AO, nullptr, 1.0f, 0,0, 0,0, 0,0);

    // 7) residual + LayerNorm
    residual_ln<<<BB * LQ, 256>>>(query, AO, gamma, beta, out);
}

// round 17
// speedup vs baseline: 1.0634x; 1.0015x over previous
#include <cuda_runtime.h>
#include <cuda_bf16.h>
#include <math.h>
#include <stdint.h>

// Problem constants
#define BB   8
#define LQ   512
#define LKV  1024
#define DD   1024
#define HH_  16
#define HD   64
#define LN_EPS 1e-5f

#define S_SCALE   4096.0f
#define S_INVSC   (1.0f / 4096.0f)
#define S_E2SC    (1.44269504088896340736f / 4096.0f)   // log2(e)/4096 (folded)

// ---------------------------------------------------------------------------
// Scratch (device globals: allocation-free per harness rules)
// ---------------------------------------------------------------------------
__device__ __align__(16) short g_S[(size_t)BB * HH_ * LQ * LKV]; // int16 scores (x4096)
__device__ float g_AO  [BB * LQ  * DD];              // fp32 attn_out
__device__ float g_rsum[BB * HH_ * LQ];              // 1/rowsum (from ctx_fused)

// bf16 buffers
__device__ __align__(16) __nv_bfloat16 g_qh [BB * LQ  * DD], g_ql [BB * LQ  * DD];
__device__ __align__(16) __nv_bfloat16 g_kh [BB * LKV * DD], g_kl [BB * LKV * DD];
__device__ __align__(16) __nv_bfloat16 g_vh [BB * LKV * DD];   // value input hi
__device__ __align__(16) __nv_bfloat16 g_vt [BB * LKV * DD];   // Vt head-major bf16
__device__ __align__(16) __nv_bfloat16 g_wh [3 * DD * DD],   g_wl [3 * DD * DD];
__device__ __align__(16) __nv_bfloat16 g_woh[DD * DD];
__device__ __align__(16) __nv_bfloat16 g_qh2[BB * LQ  * DD], g_ql2[BB * LQ  * DD];
__device__ __align__(16) __nv_bfloat16 g_kh2[BB * LKV * DD], g_kl2[BB * LKV * DD];
__device__ __align__(16) __nv_bfloat16 g_ch [BB * LQ  * DD];

// ---------------------------------------------------------------------------
// Baseline-PTX tensor-core helpers (NO tcgen05 — compute_103 target!)
// ---------------------------------------------------------------------------
__device__ __forceinline__ uint32_t smem_u32(const void* p) {
    uint32_t a;
    asm("{ .reg .u64 t; cvta.to.shared.u64 t, %1; cvt.u32.u64 %0, t; }" : "=r"(a) : "l"(p));
    return a;
}
__device__ __forceinline__ void ldsm4(uint32_t& r0, uint32_t& r1, uint32_t& r2,
                                      uint32_t& r3, uint32_t a) {
    asm volatile("ldmatrix.sync.aligned.m8n8.x4.shared.b16 {%0,%1,%2,%3}, [%4];"
                 : "=r"(r0), "=r"(r1), "=r"(r2), "=r"(r3) : "r"(a));
}
__device__ __forceinline__ void mma_bf16(float* d, const uint32_t* a, const uint32_t* b) {
    asm volatile("mma.sync.aligned.m16n8k16.row.col.f32.bf16.bf16.f32 "
                 "{%0,%1,%2,%3},{%4,%5,%6,%7},{%8,%9},{%0,%1,%2,%3};"
                 : "+f"(d[0]), "+f"(d[1]), "+f"(d[2]), "+f"(d[3])
                 : "r"(a[0]), "r"(a[1]), "r"(a[2]), "r"(a[3]), "r"(b[0]), "r"(b[1]));
}
#define CP_ASYNC16(s, g) \
    asm volatile("cp.async.cg.shared.global [%0], [%1], 16;" :: "r"(s), "l"(g))
#define CP_COMMIT() asm volatile("cp.async.commit_group;" ::: "memory")
#define CP_WAIT1()  asm volatile("cp.async.wait_group 1;"  ::: "memory")

// single-instruction packed f32x2 -> bf16x2 (lo = first arg, hi = second arg)
__device__ __forceinline__ uint32_t pack_bf16x2(float lo, float hi) {
    uint32_t r;
    asm("cvt.rn.bf16x2.f32 %0, %1, %2;" : "=r"(r) : "f"(hi), "f"(lo));
    return r;
}

// 128B-row XOR swizzle: 16B chunk c (0..7), row r
__device__ __forceinline__ uint32_t sw128(int r, int c) {
    return (uint32_t)(r * 128 + ((c ^ (r & 7)) << 4));
}
__device__ __forceinline__ void bsplit(float v, __nv_bfloat16& h, __nv_bfloat16& l) {
    h = __float2bfloat16(v);
    l = __float2bfloat16(v - __bfloat162float(h));
}
__device__ __forceinline__ short squant(float v) {
    v = fminf(fmaxf(v, -32700.f), 32700.f);
    return (short)__float2int_rn(v);
}

// ---------------------------------------------------------------------------
// One launch: split all inputs/weights (hi/lo or hi-only per segment)
// ---------------------------------------------------------------------------
__device__ __forceinline__ void seg_split2(float4 v, __nv_bfloat162* hi,
                                           __nv_bfloat162* lo, long i) {
    __nv_bfloat16 h0, h1, h2, h3, l0, l1, l2, l3;
    bsplit(v.x, h0, l0); bsplit(v.y, h1, l1);
    bsplit(v.z, h2, l2); bsplit(v.w, h3, l3);
    hi[i * 2 + 0] = __halves2bfloat162(h0, h1);
    hi[i * 2 + 1] = __halves2bfloat162(h2, h3);
    lo[i * 2 + 0] = __halves2bfloat162(l0, l1);
    lo[i * 2 + 1] = __halves2bfloat162(l2, l3);
}
__device__ __forceinline__ void seg_split1(float4 v, __nv_bfloat162* hi, long i) {
    uint32_t p0 = pack_bf16x2(v.x, v.y);
    uint32_t p1 = pack_bf16x2(v.z, v.w);
    hi[i * 2 + 0] = *(__nv_bfloat162*)&p0;
    hi[i * 2 + 1] = *(__nv_bfloat162*)&p1;
}

__global__ void split_all(const float4* __restrict__ q, const float4* __restrict__ k,
                          const float4* __restrict__ v, const float4* __restrict__ w,
                          const float4* __restrict__ wo,
                          __nv_bfloat162* qh, __nv_bfloat162* ql,
                          __nv_bfloat162* kh, __nv_bfloat162* kl,
                          __nv_bfloat162* vh,
                          __nv_bfloat162* wh, __nv_bfloat162* wl,
                          __nv_bfloat162* woh)
{
    const long N1 = (long)BB * LQ * DD / 4;
    const long N2 = N1 + (long)BB * LKV * DD / 4;
    const long N3 = N2 + (long)BB * LKV * DD / 4;
    const long N4 = N3 + 3L * DD * DD / 4;
    const long N5 = N4 + (long)DD * DD / 4;
    long i = (long)blockIdx.x * blockDim.x + threadIdx.x;
    if (i < N1)      seg_split2(q[i], qh, ql, i);
    else if (i < N2) { i -= N1; seg_split2(k[i], kh, kl, i); }
    else if (i < N3) { i -= N2; seg_split1(v[i], vh, i); }
    else if (i < N4) { i -= N3; seg_split2(w[i], wh, wl, i); }
    else if (i < N5) { i -= N4; seg_split1(wo[i], woh, i); }
}

// ---------------------------------------------------------------------------
// Merged Q/K/V projection. Grid (8, 160): y<32 Q, y<96 K, else V.
// ---------------------------------------------------------------------------
__global__ void __launch_bounds__(128, 2) qkv_proj(
    const __nv_bfloat16* __restrict__ qhp, const __nv_bfloat16* __restrict__ qlp,
    const __nv_bfloat16* __restrict__ khp, const __nv_bfloat16* __restrict__ klp,
    const __nv_bfloat16* __restrict__ vhp,
    const __nv_bfloat16* __restrict__ whp, const __nv_bfloat16* __restrict__ wlp,
    const float* __restrict__ in_b,
    __nv_bfloat16* __restrict__ qh2, __nv_bfloat16* __restrict__ ql2,
    __nv_bfloat16* __restrict__ kh2, __nv_bfloat16* __restrict__ kl2,
    __nv_bfloat16* __restrict__ vt, float qscale)
{
    extern __shared__ __align__(16) char dynsm[];
    const uint32_t smBase = smem_u32(dynsm);

    const int tid  = threadIdx.x;
    const int lane = tid & 31;
    const int wid  = tid >> 5;
    const int wr   = wid >> 1;
    const int wc   = wid & 1;
    const int y    = blockIdx.y;
    const int n0   = blockIdx.x * 128;

    int region, m0, NIT;
    float scale = 1.0f;
    const __nv_bfloat16 *Ahi, *Alo, *Bhi, *Blo;
    const float* bias;
    if (y < 32) {
        region = 0; m0 = y * 128; NIT = 48; scale = qscale;
        Ahi = qhp; Alo = qlp; Bhi = whp; Blo = wlp; bias = in_b;
    } else if (y < 96) {
        region = 1; m0 = (y - 32) * 128; NIT = 48;
        Ahi = khp; Alo = klp;
        Bhi = whp + (size_t)DD * DD; Blo = wlp + (size_t)DD * DD;
        bias = in_b + DD;
    } else {
        region = 2; m0 = (y - 96) * 128; NIT = 16;
        Ahi = vhp; Alo = vhp;
        Bhi = whp + 2ul * DD * DD; Blo = Bhi;
        bias = in_b + 2 * DD;
    }

    const int rA  = lane & 15;
    const int cAh = lane >> 4;
    const int rBl = (lane & 7) + ((lane & 16) >> 1);
    const int cBh = (lane >> 3) & 1;

    float acc[4][8][4];
#pragma unroll
    for (int mt = 0; mt < 4; ++mt)
#pragma unroll
        for (int nt = 0; nt < 8; ++nt)
#pragma unroll
            for (int j = 0; j < 4; ++j) acc[mt][nt][j] = 0.f;

    auto prefetch = [&](int it, int stage) {
        const int part = it >> 4;
        const int ko   = (it & 15) << 6;
        const __nv_bfloat16* Ap = (part == 2) ? Alo : Ahi;
        const __nv_bfloat16* Bp = (part == 1) ? Blo : Bhi;
        const uint32_t as = smBase + (uint32_t)stage * 32768u;
        const uint32_t bs = as + 16384u;
#pragma unroll
        for (int i = 0; i < 8; ++i) {
            int q = i * 128 + tid;
            int r = q >> 3, c = q & 7;
            CP_ASYNC16(as + sw128(r, c),
                       Ap + (((size_t)(m0 + r)) << 10) + ko + c * 8);
            CP_ASYNC16(bs + sw128(r, c),
                       Bp + (((size_t)(n0 + r)) << 10) + ko + c * 8);
        }
        CP_COMMIT();
    };

    prefetch(0, 0);
    prefetch(1, 1);

    for (int it = 0; it < NIT; ++it) {
        CP_WAIT1();
        __syncthreads();
        if (it + 2 < NIT) prefetch(it + 2, (it + 2) % 3);
        else CP_COMMIT();

        const uint32_t aT = smBase + (uint32_t)(it % 3) * 32768u;
        const uint32_t bT = aT + 16384u;

#pragma unroll
        for (int ks = 0; ks < 4; ++ks) {
            uint32_t af[4][4];
            uint32_t bf[8][2];
#pragma unroll
            for (int mt = 0; mt < 4; ++mt) {
                int r = wr * 64 + mt * 16 + rA;
                ldsm4(af[mt][0], af[mt][1], af[mt][2], af[mt][3],
                      aT + sw128(r, ks * 2 + cAh));
            }
#pragma unroll
            for (int tp = 0; tp < 4; ++tp) {
                int r = wc * 64 + tp * 16 + rBl;
                uint32_t x0, x1, x2, x3;
                ldsm4(x0, x1, x2, x3, bT + sw128(r, ks * 2 + cBh));
                bf[tp * 2][0] = x0;     bf[tp * 2][1] = x1;
                bf[tp * 2 + 1][0] = x2; bf[tp * 2 + 1][1] = x3;
            }
#pragma unroll
            for (int mt = 0; mt < 4; ++mt)
#pragma unroll
                for (int nt = 0; nt < 8; ++nt)
                    mma_bf16(acc[mt][nt], af[mt], bf[nt]);
        }
    }
    __syncthreads();

    if (region < 2) {
        __nv_bfloat16* Chi = region ? kh2 : qh2;
        __nv_bfloat16* Clo = region ? kl2 : ql2;
#pragma unroll
        for (int mt = 0; mt < 4; ++mt) {
            const int row = m0 + wr * 64 + mt * 16 + (lane >> 2);
#pragma unroll
            for (int nt = 0; nt < 8; ++nt) {
                const int col = n0 + wc * 64 + nt * 8 + (lane & 3) * 2;
                const float b0 = bias[col], b1 = bias[col + 1];
                const float v0 = (acc[mt][nt][0] + b0) * scale;
                const float v1 = (acc[mt][nt][1] + b1) * scale;
                const float v2 = (acc[mt][nt][2] + b0) * scale;
                const float v3 = (acc[mt][nt][3] + b1) * scale;
                const size_t i0 = ((size_t)row << 10) + col;
                const size_t i1 = i0 + (8 << 10);
                __nv_bfloat16 h0, h1, h2, h3, l0, l1, l2, l3;
                bsplit(v0, h0, l0); bsplit(v1, h1, l1);
                bsplit(v2, h2, l2); bsplit(v3, h3, l3);
                *(__nv_bfloat162*)(Chi + i0) = __halves2bfloat162(h0, h1);
                *(__nv_bfloat162*)(Clo + i0) = __halves2bfloat162(l0, l1);
                *(__nv_bfloat162*)(Chi + i1) = __halves2bfloat162(h2, h3);
                *(__nv_bfloat162*)(Clo + i1) = __halves2bfloat162(l2, l3);
            }
        }
    } else {
        // V region: bias + transpose through smem -> head-major Vt bf16.
        float* ts = (float*)dynsm;   // 128 x 128 fp32, stride 130
#pragma unroll
        for (int mt = 0; mt < 4; ++mt) {
            const int rl = wr * 64 + mt * 16 + (lane >> 2);
#pragma unroll
            for (int nt = 0; nt < 8; ++nt) {
                const int cl = wc * 64 + nt * 8 + (lane & 3) * 2;
                const float b0 = bias[n0 + cl], b1 = bias[n0 + cl + 1];
                ts[rl * 130 + cl]           = acc[mt][nt][0] + b0;
                ts[rl * 130 + cl + 1]       = acc[mt][nt][1] + b1;
                ts[(rl + 8) * 130 + cl]     = acc[mt][nt][2] + b0;
                ts[(rl + 8) * 130 + cl + 1] = acc[mt][nt][3] + b1;
            }
        }
        __syncthreads();
        const int bb = m0 >> 10;
        const int k0 = m0 & 1023;
        __nv_bfloat16* dst = vt + (((size_t)(bb * 1024 + n0 + tid)) << 10) + k0;
#pragma unroll
        for (int k = 0; k < 128; k += 8) {
            uint4 pk;
            pk.x = pack_bf16x2(ts[(k + 0) * 130 + tid], ts[(k + 1) * 130 + tid]);
            pk.y = pack_bf16x2(ts[(k + 2) * 130 + tid], ts[(k + 3) * 130 + tid]);
            pk.z = pack_bf16x2(ts[(k + 4) * 130 + tid], ts[(k + 5) * 130 + tid]);
            pk.w = pack_bf16x2(ts[(k + 6) * 130 + tid], ts[(k + 7) * 130 + tid]);
            *(uint4*)(dst + k) = pk;
        }
    }
}

// ---------------------------------------------------------------------------
// HMMA GEMM template. I16OUT=true: quantize (acc+bias)*scale to int16 (scores).
// I16OUT=false: fp32 output (out-proj).
// ---------------------------------------------------------------------------
template<int KCH, int PARTS, bool I16OUT>
__global__ void __launch_bounds__(128, 2) gemm64(
    const __nv_bfloat16* __restrict__ Ahi, const __nv_bfloat16* __restrict__ Alo,
    const __nv_bfloat16* __restrict__ Bhi, const __nv_bfloat16* __restrict__ Blo,
    const float* __restrict__ bias, float* __restrict__ Cf,
    short* __restrict__ Cs, float scale,
    long sA0, long sA1, long sB0, long sB1, long sC0, long sC1)
{
    extern __shared__ __align__(16) char dynsm[];
    const uint32_t smBase = smem_u32(dynsm);

    const int tid  = threadIdx.x;
    const int lane = tid & 31;
    const int wid  = tid >> 5;
    const int wr   = wid >> 1;
    const int wc   = wid & 1;
    const int z    = blockIdx.z;
    const int m0   = blockIdx.y * 128;
    const int n0   = blockIdx.x * 128;
    const size_t aOff = (size_t)(z >> 4) * sA0 + (size_t)(z & 15) * sA1;
    const size_t bOff = (size_t)(z >> 4) * sB0 + (size_t)(z & 15) * sB1;
    const size_t cOff = (size_t)(z >> 4) * sC0 + (size_t)(z & 15) * sC1;

    const int rA  = lane & 15;
    const int cAh = lane >> 4;
    const int rBl = (lane & 7) + ((lane & 16) >> 1);
    const int cBh = (lane >> 3) & 1;

    float acc[4][8][4];
#pragma unroll
    for (int mt = 0; mt < 4; ++mt)
#pragma unroll
        for (int nt = 0; nt < 8; ++nt)
#pragma unroll
            for (int j = 0; j < 4; ++j) acc[mt][nt][j] = 0.f;

    auto prefetch = [&](int it, int stage) {
        const int part = it / KCH;
        const int ko   = (it % KCH) << 6;
        const __nv_bfloat16* Ap = (PARTS == 3 && part == 2) ? Alo : Ahi;
        const __nv_bfloat16* Bp = (PARTS == 3 && part == 1) ? Blo : Bhi;
        const uint32_t as = smBase + (uint32_t)stage * 32768u;
        const uint32_t bs = as + 16384u;
#pragma unroll
        for (int i = 0; i < 8; ++i) {
            int q = i * 128 + tid;
            int r = q >> 3, c = q & 7;
            CP_ASYNC16(as + sw128(r, c),
                       Ap + aOff + (((size_t)(m0 + r)) << 10) + ko + c * 8);
            CP_ASYNC16(bs + sw128(r, c),
                       Bp + bOff + (((size_t)(n0 + r)) << 10) + ko + c * 8);
        }
        CP_COMMIT();
    };

    const int NIT = PARTS * KCH;
    prefetch(0, 0);
    if (NIT > 1) prefetch(1, 1);

    for (int it = 0; it < NIT; ++it) {
        CP_WAIT1();
        __syncthreads();
        if (it + 2 < NIT) prefetch(it + 2, (it + 2) % 3);
        else CP_COMMIT();

        const uint32_t aT = smBase + (uint32_t)(it % 3) * 32768u;
        const uint32_t bT = aT + 16384u;

#pragma unroll
        for (int ks = 0; ks < 4; ++ks) {
            uint32_t af[4][4];
            uint32_t bf[8][2];
#pragma unroll
            for (int mt = 0; mt < 4; ++mt) {
                int r = wr * 64 + mt * 16 + rA;
                ldsm4(af[mt][0], af[mt][1], af[mt][2], af[mt][3],
                      aT + sw128(r, ks * 2 + cAh));
            }
#pragma unroll
            for (int tp = 0; tp < 4; ++tp) {
                int r = wc * 64 + tp * 16 + rBl;
                uint32_t x0, x1, x2, x3;
                ldsm4(x0, x1, x2, x3, bT + sw128(r, ks * 2 + cBh));
                bf[tp * 2][0] = x0;     bf[tp * 2][1] = x1;
                bf[tp * 2 + 1][0] = x2; bf[tp * 2 + 1][1] = x3;
            }
#pragma unroll
            for (int mt = 0; mt < 4; ++mt)
#pragma unroll
                for (int nt = 0; nt < 8; ++nt)
                    mma_bf16(acc[mt][nt], af[mt], bf[nt]);
        }
    }
    __syncthreads();

#pragma unroll
    for (int mt = 0; mt < 4; ++mt) {
        const int row = m0 + wr * 64 + mt * 16 + (lane >> 2);
#pragma unroll
        for (int nt = 0; nt < 8; ++nt) {
            const int col = n0 + wc * 64 + nt * 8 + (lane & 3) * 2;
            const float b0 = bias ? bias[col]     : 0.f;
            const float b1 = bias ? bias[col + 1] : 0.f;
            const float v0 = (acc[mt][nt][0] + b0) * scale;
            const float v1 = (acc[mt][nt][1] + b1) * scale;
            const float v2 = (acc[mt][nt][2] + b0) * scale;
            const float v3 = (acc[mt][nt][3] + b1) * scale;
            const size_t i0 = cOff + ((size_t)row << 10) + col;
            const size_t i1 = i0 + (8 << 10);
            if (I16OUT) {
                *(short2*)(Cs + i0) = make_short2(squant(v0), squant(v1));
                *(short2*)(Cs + i1) = make_short2(squant(v2), squant(v3));
            } else {
                Cf[i0] = v0; Cf[i0 + 1] = v1;
                Cf[i1] = v2; Cf[i1 + 1] = v3;
            }
        }
    }
}

// ---------------------------------------------------------------------------
// Head-mean of softmax(S) using precomputed 1/rowsum from ctx_fused.
// ---------------------------------------------------------------------------
__global__ void __launch_bounds__(512) mean_heads(const short* __restrict__ S,
                                                  const float* __restrict__ rinv,
                                                  float* __restrict__ mean_out)
{
    __shared__ float part[4][1024];
    __shared__ float sinv[16];
    const int bq = blockIdx.x;
    const int b = bq >> 9, q = bq & 511;
    const int tid = threadIdx.x;
    const int hg = tid >> 7;
    const int kb = (tid & 127) * 8;

    if (tid < 16) sinv[tid] = __ldg(&rinv[(size_t)(b * 16 + tid) * 512 + q]);
    __syncthreads();

    float macc[8];
#pragma unroll
    for (int j = 0; j < 8; ++j) macc[j] = 0.f;

#pragma unroll
    for (int i = 0; i < 4; ++i) {
        const int h = hg + i * 4;
        const float inv = sinv[h];
        int4 raw = __ldg((const int4*)(S + (((size_t)(b * 16 + h) * 512 + q) << 10) + kb));
        const uint32_t* u = (const uint32_t*)&raw;
#pragma unroll
        for (int j = 0; j < 4; ++j) {
            macc[j * 2 + 0] += exp2f((float)((short)(u[j] & 0xFFFF)) * S_E2SC) * inv;
            macc[j * 2 + 1] += exp2f((float)((short)(u[j] >> 16))    * S_E2SC) * inv;
        }
    }
    *(float4*)&part[hg][kb]     = make_float4(macc[0], macc[1], macc[2], macc[3]);
    *(float4*)&part[hg][kb + 4] = make_float4(macc[4], macc[5], macc[6], macc[7]);
    __syncthreads();

    const float inv16 = 1.0f / HH_;
    float* mo = mean_out + (((size_t)bq) << 10);
    float s0 = (part[0][tid] + part[1][tid]) + (part[2][tid] + part[3][tid]);
    float s1 = (part[0][tid + 512] + part[1][tid + 512]) +
               (part[2][tid + 512] + part[3][tid + 512]);
    mo[tid]       = s0 * inv16;
    mo[tid + 512] = s1 * inv16;
}

// ---------------------------------------------------------------------------
// Fused ctx (plain bf16), SELF-NORMALIZING, exports 1/rowsum to global.
// Conversion stream uses folded exp2f + single-instruction bf16x2 packs.
// ---------------------------------------------------------------------------
__global__ void __launch_bounds__(512) ctx_fused(
    const short* __restrict__ S,
    const __nv_bfloat16* __restrict__ Vhi,
    __nv_bfloat16* __restrict__ Chi, float* __restrict__ rinv_out)
{
    extern __shared__ __align__(16) char dynsm[];
    const uint32_t smBase = smem_u32(dynsm);
    float* rs = (float*)(dynsm + 32768 + 3 * 8192);   // [128] row sums

    const int tid  = threadIdx.x;
    const int lane = tid & 31;
    const int wid  = tid >> 5;
    const int wr   = wid >> 2;
    const int wc   = wid & 3;
    const int z    = blockIdx.z, b = z >> 4, h = z & 15;
    const int m0   = blockIdx.y * 128;
    const size_t sOff  = ((size_t)z * 512 + m0) << 10;
    const size_t vOff  = ((size_t)z * 64) << 10;

    const int rA  = lane & 15;
    const int cAh = lane >> 4;
    const int rBl = (lane & 7) + ((lane & 16) >> 1);
    const int cBh = (lane >> 3) & 1;

    float acc[2][2][4];
#pragma unroll
    for (int mt = 0; mt < 2; ++mt)
#pragma unroll
        for (int nt = 0; nt < 2; ++nt)
#pragma unroll
            for (int j = 0; j < 4; ++j) acc[mt][nt][j] = 0.f;

    float rsum0 = 0.f, rsum1 = 0.f;

    int4 sreg[2];
    auto ldS = [&](int kc) {
#pragma unroll
        for (int i = 0; i < 2; ++i) {
            int idx = i * 512 + tid;
            int row = idx >> 3, c8 = idx & 7;
            sreg[i] = __ldg((const int4*)(S + sOff + ((size_t)row << 10) +
                                          (kc << 6) + c8 * 8));
        }
    };
    auto cpV = [&](int kc) {
        const uint32_t vs = smBase + 32768u + (uint32_t)(kc % 3) * 8192u;
        int r = tid >> 3, c = tid & 7;
        CP_ASYNC16(vs + sw128(r, c), Vhi + vOff + ((size_t)r << 10) + (kc << 6) + c * 8);
        CP_COMMIT();
    };

    ldS(0);
    cpV(0);
    cpV(1);

    for (int kc = 0; kc < 16; ++kc) {
        const uint32_t pB = smBase + (uint32_t)(kc & 1) * 16384u;
#pragma unroll
        for (int i = 0; i < 2; ++i) {
            int idx = i * 512 + tid;
            int row = idx >> 3, c8 = idx & 7;
            const uint32_t* u = (const uint32_t*)&sreg[i];
            uint32_t packed[4];
            float esum = 0.f;
#pragma unroll
            for (int j = 0; j < 4; ++j) {
                float a = exp2f((float)((short)(u[j] & 0xFFFF)) * S_E2SC);
                float c = exp2f((float)((short)(u[j] >> 16))    * S_E2SC);
                esum += a + c;
                packed[j] = pack_bf16x2(a, c);
            }
            if (i == 0) rsum0 += esum; else rsum1 += esum;
            uint32_t off = sw128(row, c8);
            asm volatile("st.shared.v4.b32 [%0], {%1, %2, %3, %4};" ::
                         "r"(pB + off), "r"(packed[0]), "r"(packed[1]),
                         "r"(packed[2]), "r"(packed[3]) : "memory");
        }
        if (kc + 1 < 16) ldS(kc + 1);

        CP_WAIT1();
        __syncthreads();
        if (kc + 2 < 16) cpV(kc + 2);
        else CP_COMMIT();

        const uint32_t phT = smBase + (uint32_t)(kc & 1) * 16384u;
        const uint32_t vhT = smBase + 32768u + (uint32_t)(kc % 3) * 8192u;

#pragma unroll
        for (int ks = 0; ks < 4; ++ks) {
            uint32_t ah[2][4];
            uint32_t bh[2][2];
#pragma unroll
            for (int mt = 0; mt < 2; ++mt) {
                int r = wr * 32 + mt * 16 + rA;
                ldsm4(ah[mt][0], ah[mt][1], ah[mt][2], ah[mt][3],
                      phT + sw128(r, ks * 2 + cAh));
            }
            {
                int r = wc * 16 + rBl;
                uint32_t x0, x1, x2, x3;
                ldsm4(x0, x1, x2, x3, vhT + sw128(r, ks * 2 + cBh));
                bh[0][0] = x0; bh[0][1] = x1; bh[1][0] = x2; bh[1][1] = x3;
            }
#pragma unroll
            for (int mt = 0; mt < 2; ++mt)
#pragma unroll
                for (int nt = 0; nt < 2; ++nt)
                    mma_bf16(acc[mt][nt], ah[mt], bh[nt]);
        }
    }

    // combine row sums: octet shuffle, then smem
#pragma unroll
    for (int o = 1; o < 8; o <<= 1) {
        rsum0 += __shfl_xor_sync(0xffffffffu, rsum0, o);
        rsum1 += __shfl_xor_sync(0xffffffffu, rsum1, o);
    }
    if ((tid & 7) == 0) {
        rs[tid >> 3]        = rsum0;
        rs[(tid >> 3) + 64] = rsum1;
    }
    __syncthreads();

    // export 1/rowsum for mean_heads
    if (tid < 128)
        rinv_out[(size_t)z * 512 + m0 + tid] = 1.0f / rs[tid];

#pragma unroll
    for (int mt = 0; mt < 2; ++mt) {
        const int rl = wr * 32 + mt * 16 + (lane >> 2);
        const float inv0 = 1.0f / rs[rl];
        const float inv1 = 1.0f / rs[rl + 8];
        const int row = m0 + rl;
#pragma unroll
        for (int nt = 0; nt < 2; ++nt) {
            const int col = h * 64 + wc * 16 + nt * 8 + (lane & 3) * 2;
            const size_t i0 = (((size_t)(b * 512 + row)) << 10) + col;
            const size_t i1 = i0 + (8 << 10);
            uint32_t p0 = pack_bf16x2(acc[mt][nt][0] * inv0, acc[mt][nt][1] * inv0);
            uint32_t p1 = pack_bf16x2(acc[mt][nt][2] * inv1, acc[mt][nt][3] * inv1);
            *(uint32_t*)(Chi + i0) = p0;
            *(uint32_t*)(Chi + i1) = p1;
        }
    }
}

// ---------------------------------------------------------------------------
// out = LayerNorm(query + attn_out) * gamma + beta.  One block per row.
// ---------------------------------------------------------------------------
__global__ void residual_ln(const float* __restrict__ q, const float* __restrict__ ao,
                            const float* __restrict__ gamma, const float* __restrict__ beta,
                            float* __restrict__ out)
{
    __shared__ float red[8];
    __shared__ float bcast;
    const long row = blockIdx.x;
    const int tid = threadIdx.x;

    float4 qa = *(const float4*)&q [row * DD + tid * 4];
    float4 aa = *(const float4*)&ao[row * DD + tid * 4];
    float x0 = qa.x + aa.x, x1 = qa.y + aa.y, x2 = qa.z + aa.z, x3 = qa.w + aa.w;

    float s = (x0 + x1) + (x2 + x3);
#pragma unroll
    for (int o = 16; o; o >>= 1) s += __shfl_xor_sync(0xffffffffu, s, o);
    if ((tid & 31) == 0) red[tid >> 5] = s;
    __syncthreads();
    if (tid < 8) {
        s = red[tid];
#pragma unroll
        for (int o = 4; o; o >>= 1) s += __shfl_xor_sync(0xffu, s, o);
        if (tid == 0) bcast = s;
    }
    __syncthreads();
    const float mu = bcast * (1.0f / DD);

    float d0 = x0 - mu, d1 = x1 - mu, d2 = x2 - mu, d3 = x3 - mu;
    float sq = (d0 * d0 + d1 * d1) + (d2 * d2 + d3 * d3);
#pragma unroll
    for (int o = 16; o; o >>= 1) sq += __shfl_xor_sync(0xffffffffu, sq, o);
    __syncthreads();
    if ((tid & 31) == 0) red[tid >> 5] = sq;
    __syncthreads();
    if (tid < 8) {
        sq = red[tid];
#pragma unroll
        for (int o = 4; o; o >>= 1) sq += __shfl_xor_sync(0xffu, sq, o);
        if (tid == 0) bcast = sq;
    }
    __syncthreads();
    const float rstd = rsqrtf(bcast * (1.0f / DD) + LN_EPS);

    float4 g = *(const float4*)&gamma[tid * 4];
    float4 be = *(const float4*)&beta[tid * 4];
    float4 o4;
    o4.x = d0 * rstd * g.x + be.x;
    o4.y = d1 * rstd * g.y + be.y;
    o4.z = d2 * rstd * g.z + be.z;
    o4.w = d3 * rstd * g.w + be.w;
    *(float4*)&out[row * DD + tid * 4] = o4;
}

// ---------------------------------------------------------------------------
extern "C" void kernel_launch(void* const* d_in, const int* in_sizes, int n_in,
                              void* d_out, int out_size)
{
    const float* query = (const float*)d_in[0];
    const float* key_  = (const float*)d_in[1];
    const float* value = (const float*)d_in[2];
    const float* in_w  = (const float*)d_in[3];
    const float* in_b  = (const float*)d_in[4];
    const float* out_w = (const float*)d_in[5];
    const float* out_b = (const float*)d_in[6];
    const float* gamma = (const float*)d_in[7];
    const float* beta  = (const float*)d_in[8];
    float* out = (float*)d_out;

    short* Si;
    float *AO, *RI;
    cudaGetSymbolAddress((void**)&Si, g_S);
    cudaGetSymbolAddress((void**)&AO, g_AO);
    cudaGetSymbolAddress((void**)&RI, g_rsum);

    __nv_bfloat16 *qh, *ql, *kh, *kl, *vh, *vt, *wh, *wl, *woh;
    __nv_bfloat16 *qh2, *ql2, *kh2, *kl2, *ch;
    cudaGetSymbolAddress((void**)&qh,  g_qh);  cudaGetSymbolAddress((void**)&ql,  g_ql);
    cudaGetSymbolAddress((void**)&kh,  g_kh);  cudaGetSymbolAddress((void**)&kl,  g_kl);
    cudaGetSymbolAddress((void**)&vh,  g_vh);  cudaGetSymbolAddress((void**)&vt,  g_vt);
    cudaGetSymbolAddress((void**)&wh,  g_wh);  cudaGetSymbolAddress((void**)&wl,  g_wl);
    cudaGetSymbolAddress((void**)&woh, g_woh);
    cudaGetSymbolAddress((void**)&qh2, g_qh2); cudaGetSymbolAddress((void**)&ql2, g_ql2);
    cudaGetSymbolAddress((void**)&kh2, g_kh2); cudaGetSymbolAddress((void**)&kl2, g_kl2);
    cudaGetSymbolAddress((void**)&ch,  g_ch);

    const int SM_G = 3 * 32768;
    const int SM_X = 2 * 16384 + 3 * 8192 + 512;
    cudaFuncSetAttribute((const void*)qkv_proj,
                         cudaFuncAttributeMaxDynamicSharedMemorySize, SM_G);
    cudaFuncSetAttribute((const void*)gemm64<1, 3, true>,
                         cudaFuncAttributeMaxDynamicSharedMemorySize, SM_G);
    cudaFuncSetAttribute((const void*)gemm64<16, 1, false>,
                         cudaFuncAttributeMaxDynamicSharedMemorySize, SM_G);
    cudaFuncSetAttribute((const void*)ctx_fused,
                         cudaFuncAttributeMaxDynamicSharedMemorySize, SM_X);

    const float qscale = 0.125f;

    // 1) split everything in one launch
    {
        const long total4 = (long)BB*LQ*DD/4 + 2L*BB*LKV*DD/4 + 3L*DD*DD/4 + (long)DD*DD/4;
        split_all<<<(unsigned)((total4 + 255) / 256), 256>>>(
            (const float4*)query, (const float4*)key_, (const float4*)value,
            (const float4*)in_w, (const float4*)out_w,
            (__nv_bfloat162*)qh, (__nv_bfloat162*)ql,
            (__nv_bfloat162*)kh, (__nv_bfloat162*)kl,
            (__nv_bfloat162*)vh,
            (__nv_bfloat162*)wh, (__nv_bfloat162*)wl,
            (__nv_bfloat162*)woh);
    }

    // 2) merged Q/K/V projection (+ fused V transpose -> vt)
    qkv_proj<<<dim3(8, 160), 128, SM_G>>>(
        qh, ql, kh, kl, vh, wh, wl, in_b,
        qh2, ql2, kh2, kl2, vt, qscale);

    // 3) scores (bf16x3) -> int16 S (scaled by 4096)
    gemm64<1, 3, true><<<dim3(8, 4, BB * HH_), 128, SM_G>>>(
        qh2, ql2, kh2, kl2, nullptr, nullptr, Si, S_SCALE,
        (long)LQ * DD,  (long)HD,
        (long)LKV * DD, (long)HD,
        (long)HH_ * LQ * LKV, (long)LQ * LKV);

    // 4) fused self-normalizing ctx MMA; exports 1/rowsum
    ctx_fused<<<dim3(1, 4, BB * HH_), 512, SM_X>>>(Si, vt, ch, RI);

    // 5) head-mean of softmax using exported rowsums
    mean_heads<<<BB * LQ, 512>>>(Si, RI, out + (long)BB * LQ * DD);

    // 6) out projection (bf16x1) -> fp32 AO
    gemm64<16, 1, false><<<dim3(8, 32, 1), 128, SM_G>>>(
        ch, nullptr, woh, nullptr, out_b, AO, nullptr, 1.0f, 0,0, 0,0, 0,0);

    // 7) residual + LayerNorm
    residual_ln<<<BB * LQ, 256>>>(query, AO, gamma, beta, out);
}